// round 8
// baseline (speedup 1.0000x reference)
#include <cuda_runtime.h>
#include <cuda_bf16.h>
#include <cstdint>

#define N_NODES 50000
#define IN_C    256
#define HID     128
#define N_EDGES 800000
#define SCAN_B  256
#define SCAN_NB ((N_NODES + SCAN_B - 1) / SCAN_B)   // 196

// ---- device scratch: referenced ONLY from device code (never passed from host!) ----
__device__ float g_hs[N_NODES * HID];      // (x @ W_conv) * dinv[row]
__device__ int   g_count[N_NODES];
__device__ int   g_rowptr[N_NODES + 1];
__device__ int   g_cursor[N_NODES];
__device__ int   g_col[N_EDGES];
__device__ float g_dinv[N_NODES];
__device__ float g_bias2[IN_C];
__device__ int   g_blocksum[SCAN_NB];
// bf16 split of x and W_conv^T (N-major) for HMMA GEMM1
__device__ __nv_bfloat16 g_xhi[N_NODES * IN_C];
__device__ __nv_bfloat16 g_xlo[N_NODES * IN_C];
__device__ __nv_bfloat16 g_wchi[HID * IN_C];   // [n][k] = W_conv[k][n]
__device__ __nv_bfloat16 g_wclo[HID * IN_C];

// ================= CSR build =================
__global__ void k_count_init() {
    for (int i = blockIdx.x * blockDim.x + threadIdx.x; i < N_NODES;
         i += gridDim.x * blockDim.x)
        g_count[i] = 0;
}

__global__ void k_count(const int* __restrict__ dst) {
    for (int e = blockIdx.x * blockDim.x + threadIdx.x; e < N_EDGES;
         e += gridDim.x * blockDim.x)
        atomicAdd(&g_count[dst[e]], 1);
}

__global__ void k_scan1() {
    __shared__ int sh[SCAN_B];
    int i = blockIdx.x * SCAN_B + threadIdx.x;
    int v = (i < N_NODES) ? g_count[i] : 0;
    sh[threadIdx.x] = v;
    __syncthreads();
    #pragma unroll
    for (int o = 1; o < SCAN_B; o <<= 1) {
        int t = (threadIdx.x >= o) ? sh[threadIdx.x - o] : 0;
        __syncthreads();
        sh[threadIdx.x] += t;
        __syncthreads();
    }
    if (i < N_NODES) g_rowptr[i] = sh[threadIdx.x] - v;
    if (threadIdx.x == SCAN_B - 1) g_blocksum[blockIdx.x] = sh[SCAN_B - 1];
}

__global__ void k_scan2() {
    __shared__ int sh[256];
    int v = (threadIdx.x < SCAN_NB) ? g_blocksum[threadIdx.x] : 0;
    sh[threadIdx.x] = v;
    __syncthreads();
    #pragma unroll
    for (int o = 1; o < 256; o <<= 1) {
        int t = (threadIdx.x >= o) ? sh[threadIdx.x - o] : 0;
        __syncthreads();
        sh[threadIdx.x] += t;
        __syncthreads();
    }
    if (threadIdx.x < SCAN_NB) g_blocksum[threadIdx.x] = sh[threadIdx.x] - v;
}

__global__ void k_scan3() {
    int i = blockIdx.x * SCAN_B + threadIdx.x;
    if (i < N_NODES) {
        int r = g_rowptr[i] + g_blocksum[i / SCAN_B];
        g_rowptr[i] = r;
        g_cursor[i] = r;
        g_dinv[i]   = rsqrtf((float)(g_count[i] + 1));   // +1 self loop
    }
    if (i == 0 && blockIdx.x == 0) g_rowptr[N_NODES] = N_EDGES;
}

__global__ void k_fill(const int* __restrict__ src, const int* __restrict__ dst) {
    for (int e = blockIdx.x * blockDim.x + threadIdx.x; e < N_EDGES;
         e += gridDim.x * blockDim.x) {
        int p = atomicAdd(&g_cursor[dst[e]], 1);
        g_col[p] = src[e];
    }
}

// ================= bf16 split prep =================
__global__ void k_split_x(const float* __restrict__ x) {
    for (int i = blockIdx.x * blockDim.x + threadIdx.x; i < N_NODES * IN_C;
         i += gridDim.x * blockDim.x) {
        float v = x[i];
        __nv_bfloat16 h = __float2bfloat16(v);
        g_xhi[i] = h;
        g_xlo[i] = __float2bfloat16(v - __bfloat162float(h));
    }
}

__global__ void k_split_wc(const float* __restrict__ W_conv) {
    for (int i = blockIdx.x * blockDim.x + threadIdx.x; i < IN_C * HID;
         i += gridDim.x * blockDim.x) {
        int k = i / HID, n = i % HID;
        float v = W_conv[i];
        __nv_bfloat16 h = __float2bfloat16(v);
        g_wchi[n * IN_C + k] = h;
        g_wclo[n * IN_C + k] = __float2bfloat16(v - __bfloat162float(h));
    }
}

// ================= bias fold =================
__global__ void k_bias2(const float* __restrict__ b_conv,
                        const float* __restrict__ W_lin,
                        const float* __restrict__ b_lin) {
    int j = blockIdx.x * blockDim.x + threadIdx.x;
    if (j < IN_C) {
        float s = b_lin[j];
        #pragma unroll 4
        for (int k = 0; k < HID; k++) s += b_conv[k] * W_lin[k * IN_C + j];
        g_bias2[j] = s;
    }
}

// ================= HMMA helpers =================
__device__ __forceinline__ void mma_bf16(float& c0, float& c1, float& c2, float& c3,
                                         uint32_t a0, uint32_t a1, uint32_t a2, uint32_t a3,
                                         uint32_t b0, uint32_t b1) {
    asm volatile(
        "mma.sync.aligned.m16n8k16.row.col.f32.bf16.bf16.f32 "
        "{%0,%1,%2,%3}, {%4,%5,%6,%7}, {%8,%9}, {%0,%1,%2,%3};"
        : "+f"(c0), "+f"(c1), "+f"(c2), "+f"(c3)
        : "r"(a0), "r"(a1), "r"(a2), "r"(a3), "r"(b0), "r"(b1));
}

// ================= GEMM1 via mma.sync bf16 (hi/lo split) =================
// Block: 128 rows x 128 cols; 256 threads = 8 warps in 4(m) x 2(n) grid.
// Warp tile: 32(m) x 64(n) = 2 m-tiles x 8 n-tiles of m16n8k16.
// W^T (hi+lo) staged fully in smem (padded rows); A streamed per 16-wide K chunk.
#define W_STRIDE 264                         // bf16 elems per smem W row (padding kills conflicts)
#define SW_HI    0
#define SW_LO    (HID * W_STRIDE * 2)        // 67584
#define SA_HI    (2 * HID * W_STRIDE * 2)    // 135168
#define SA_LO    (SA_HI + 4096)
#define G1_SMEM  (SA_LO + 4096)              // 143360 bytes

__global__ __launch_bounds__(256, 1)
void gemm1_mma() {
    extern __shared__ char smem[];
    const int tid  = threadIdx.x;
    const int wid  = tid >> 5;
    const int lane = tid & 31;
    const int g    = lane >> 2;       // group 0..7
    const int tg   = lane & 3;        // thread-in-group 0..3
    const int wm   = wid >> 1;        // 0..3
    const int wn   = wid & 1;         // 0..1
    const int rowBase = blockIdx.x * 128;

    // ---- stage W^T hi/lo into padded smem (once) ----
    // each array: 128 n-rows x 256 k (512B payload per row, 528B stride)
    for (int idx = tid; idx < 128 * 32; idx += 256) {
        int n = idx >> 5;
        int q = idx & 31;             // 16B group within row
        *reinterpret_cast<uint4*>(smem + SW_HI + n * (W_STRIDE * 2) + q * 16) =
            *reinterpret_cast<const uint4*>(&g_wchi[n * IN_C + q * 8]);
        *reinterpret_cast<uint4*>(smem + SW_LO + n * (W_STRIDE * 2) + q * 16) =
            *reinterpret_cast<const uint4*>(&g_wclo[n * IN_C + q * 8]);
    }

    float c[2][8][4];
    #pragma unroll
    for (int mt = 0; mt < 2; mt++)
        #pragma unroll
        for (int nt = 0; nt < 8; nt++)
            #pragma unroll
            for (int q = 0; q < 4; q++) c[mt][nt][q] = 0.0f;

    __syncthreads();

    for (int kc = 0; kc < 16; kc++) {            // K chunks of 16
        // ---- stage A chunk [128 rows x 16 k] hi/lo ----
        {
            int r    = tid >> 1;
            int half = tid & 1;
            int grow = rowBase + r;
            uint4 vh = make_uint4(0, 0, 0, 0), vl = make_uint4(0, 0, 0, 0);
            if (grow < N_NODES) {
                size_t off = (size_t)grow * IN_C + kc * 16 + half * 8;
                vh = *reinterpret_cast<const uint4*>(&g_xhi[off]);
                vl = *reinterpret_cast<const uint4*>(&g_xlo[off]);
            }
            *reinterpret_cast<uint4*>(smem + SA_HI + r * 32 + half * 16) = vh;
            *reinterpret_cast<uint4*>(smem + SA_LO + r * 32 + half * 16) = vl;
        }
        __syncthreads();

        // ---- A fragments (2 m-tiles, hi+lo) ----
        uint32_t ah[2][4], al[2][4];
        #pragma unroll
        for (int mt = 0; mt < 2; mt++) {
            int row = wm * 32 + mt * 16 + g;
            int base = row * 32 + tg * 4;
            ah[mt][0] = *reinterpret_cast<uint32_t*>(smem + SA_HI + base);
            ah[mt][1] = *reinterpret_cast<uint32_t*>(smem + SA_HI + base + 8 * 32);
            ah[mt][2] = *reinterpret_cast<uint32_t*>(smem + SA_HI + base + 16);
            ah[mt][3] = *reinterpret_cast<uint32_t*>(smem + SA_HI + base + 8 * 32 + 16);
            al[mt][0] = *reinterpret_cast<uint32_t*>(smem + SA_LO + base);
            al[mt][1] = *reinterpret_cast<uint32_t*>(smem + SA_LO + base + 8 * 32);
            al[mt][2] = *reinterpret_cast<uint32_t*>(smem + SA_LO + base + 16);
            al[mt][3] = *reinterpret_cast<uint32_t*>(smem + SA_LO + base + 8 * 32 + 16);
        }

        // ---- B fragments (8 n-tiles, hi+lo) + MMAs ----
        #pragma unroll
        for (int nt = 0; nt < 8; nt++) {
            int n = wn * 64 + nt * 8 + g;
            int base = n * (W_STRIDE * 2) + kc * 32 + tg * 4;
            uint32_t bh0 = *reinterpret_cast<uint32_t*>(smem + SW_HI + base);
            uint32_t bh1 = *reinterpret_cast<uint32_t*>(smem + SW_HI + base + 16);
            uint32_t bl0 = *reinterpret_cast<uint32_t*>(smem + SW_LO + base);
            uint32_t bl1 = *reinterpret_cast<uint32_t*>(smem + SW_LO + base + 16);
            #pragma unroll
            for (int mt = 0; mt < 2; mt++) {
                mma_bf16(c[mt][nt][0], c[mt][nt][1], c[mt][nt][2], c[mt][nt][3],
                         ah[mt][0], ah[mt][1], ah[mt][2], ah[mt][3], bh0, bh1);
                mma_bf16(c[mt][nt][0], c[mt][nt][1], c[mt][nt][2], c[mt][nt][3],
                         ah[mt][0], ah[mt][1], ah[mt][2], ah[mt][3], bl0, bl1);
                mma_bf16(c[mt][nt][0], c[mt][nt][1], c[mt][nt][2], c[mt][nt][3],
                         al[mt][0], al[mt][1], al[mt][2], al[mt][3], bh0, bh1);
            }
        }
        __syncthreads();
    }

    // ---- epilogue: scale by dinv[row], store to g_hs ----
    #pragma unroll
    for (int mt = 0; mt < 2; mt++) {
        int r0 = rowBase + wm * 32 + mt * 16 + g;
        int r1 = r0 + 8;
        float dv0 = (r0 < N_NODES) ? g_dinv[r0] : 0.0f;
        float dv1 = (r1 < N_NODES) ? g_dinv[r1] : 0.0f;
        #pragma unroll
        for (int nt = 0; nt < 8; nt++) {
            int col = wn * 64 + nt * 8 + tg * 2;
            if (r0 < N_NODES) {
                float2 v = make_float2(c[mt][nt][0] * dv0, c[mt][nt][1] * dv0);
                *reinterpret_cast<float2*>(&g_hs[(size_t)r0 * HID + col]) = v;
            }
            if (r1 < N_NODES) {
                float2 v = make_float2(c[mt][nt][2] * dv1, c[mt][nt][3] * dv1);
                *reinterpret_cast<float2*>(&g_hs[(size_t)r1 * HID + col]) = v;
            }
        }
    }
}

// ================= FUSED gather + GEMM2 (proven, unchanged) =================
__global__ __launch_bounds__(256, 2)
void k_fused(const float* __restrict__ W_lin,
             float* __restrict__ out) {
    __shared__ float sAgg[64][HID];    // 32 KB
    __shared__ float sB[8][IN_C];      // 8 KB

    const int tid = threadIdx.x;       // 256
    const int w   = tid >> 5;
    const int l   = tid & 31;
    const int rowBase = blockIdx.x * 64;

    const float4* hs4 = reinterpret_cast<const float4*>(g_hs);
    #pragma unroll
    for (int q = 0; q < 8; q++) {
        int nLocal = w * 8 + q;
        int i = rowBase + nLocal;
        float4 acc = make_float4(0.f, 0.f, 0.f, 0.f);
        if (i < N_NODES) {
            acc = hs4[(size_t)i * (HID / 4) + l];
            int beg = g_rowptr[i];
            int end = g_rowptr[i + 1];
            for (int e = beg; e < end; e++) {
                int j = g_col[e];
                float4 v = hs4[(size_t)j * (HID / 4) + l];
                acc.x += v.x; acc.y += v.y; acc.z += v.z; acc.w += v.w;
            }
            float dv = g_dinv[i];
            acc.x *= dv; acc.y *= dv; acc.z *= dv; acc.w *= dv;
        }
        *reinterpret_cast<float4*>(&sAgg[nLocal][l * 4]) = acc;
    }
    __syncthreads();

    const int tx = tid & 31;
    const int ty = tid >> 5;

    float acc[8][8];
    {
        float bj[8];
        #pragma unroll
        for (int j = 0; j < 8; j++) bj[j] = g_bias2[tx * 8 + j];
        #pragma unroll
        for (int i = 0; i < 8; i++)
            #pragma unroll
            for (int j = 0; j < 8; j++) acc[i][j] = bj[j];
    }

    for (int k0 = 0; k0 < HID; k0 += 8) {
        #pragma unroll
        for (int q = 0; q < 2; q++) {
            int lin = (q * 256 + tid) * 4;
            int r = lin >> 8;
            int c = lin & 255;
            *reinterpret_cast<float4*>(&sB[r][c]) =
                *reinterpret_cast<const float4*>(&W_lin[(size_t)(k0 + r) * IN_C + c]);
        }
        __syncthreads();

        #pragma unroll
        for (int k = 0; k < 8; k++) {
            float a[8];
            #pragma unroll
            for (int i = 0; i < 8; i++) a[i] = sAgg[ty * 8 + i][k0 + k];
            float4 b0 = *reinterpret_cast<const float4*>(&sB[k][tx * 8]);
            float4 b1 = *reinterpret_cast<const float4*>(&sB[k][tx * 8 + 4]);
            float b[8] = {b0.x, b0.y, b0.z, b0.w, b1.x, b1.y, b1.z, b1.w};
            #pragma unroll
            for (int i = 0; i < 8; i++)
                #pragma unroll
                for (int j = 0; j < 8; j++)
                    acc[i][j] += a[i] * b[j];
        }
        __syncthreads();
    }

    float4* out4 = reinterpret_cast<float4*>(out);
    #pragma unroll
    for (int i = 0; i < 8; i++) {
        int grow = rowBase + ty * 8 + i;
        if (grow >= N_NODES) continue;
        float4 v0 = make_float4(acc[i][0], acc[i][1], acc[i][2], acc[i][3]);
        float4 v1 = make_float4(acc[i][4], acc[i][5], acc[i][6], acc[i][7]);
        out4[(size_t)grow * (IN_C / 4) + tx * 2 + 0] = v0;
        out4[(size_t)grow * (IN_C / 4) + tx * 2 + 1] = v1;
    }
}

// ================= launch =================
extern "C" void kernel_launch(void* const* d_in, const int* in_sizes, int n_in,
                              void* d_out, int out_size) {
    const float* x      = nullptr;
    const int*   eidx   = nullptr;
    const float* W_conv = nullptr;
    const float* W_lin  = nullptr;
    const float* b_conv = nullptr;
    const float* b_lin  = nullptr;

    for (int i = 0; i < n_in; i++) {
        int sz = in_sizes[i];
        const void* p = d_in[i];
        if      (sz == N_NODES * IN_C) x = (const float*)p;
        else if (sz == 2 * N_EDGES)    eidx = (const int*)p;
        else if (sz == IN_C * HID) { if (!W_conv) W_conv = (const float*)p;
                                     else         W_lin  = (const float*)p; }
        else if (sz == HID)            b_conv = (const float*)p;
        else if (sz == IN_C)           b_lin  = (const float*)p;
    }
    if (!x || !eidx || !W_conv || !W_lin || !b_conv || !b_lin) {
        x      = (const float*)d_in[0];
        eidx   = (const int*)d_in[1];
        W_conv = (const float*)d_in[2];
        b_conv = (const float*)d_in[3];
        W_lin  = (const float*)d_in[4];
        b_lin  = (const float*)d_in[5];
    }

    float* out = (float*)d_out;
    const int* src = eidx;
    const int* dst = eidx + N_EDGES;

    // CSR build + normalization
    k_count_init<<<196, 256>>>();
    k_count<<<3125, 256>>>(dst);
    k_scan1<<<SCAN_NB, SCAN_B>>>();
    k_scan2<<<1, 256>>>();
    k_scan3<<<SCAN_NB, SCAN_B>>>();
    k_fill<<<3125, 256>>>(src, dst);

    // bf16 split prep
    k_split_x<<<3125, 256>>>(x);
    k_split_wc<<<128, 256>>>(W_conv);

    // bias fold
    k_bias2<<<2, 128>>>(b_conv, W_lin, b_lin);

    // GEMM1 via HMMA: g_hs = (x @ W_conv) * dinv[row]
    static bool attr_set = false;
    if (!attr_set) {
        cudaFuncSetAttribute(gemm1_mma, cudaFuncAttributeMaxDynamicSharedMemorySize, G1_SMEM);
        attr_set = true;
    }
    gemm1_mma<<<(N_NODES + 127) / 128, 256, G1_SMEM>>>();

    // FUSED gather + GEMM2 -> out
    k_fused<<<(N_NODES + 63) / 64, 256>>>(W_lin, out);
}

// round 9
// speedup vs baseline: 1.4141x; 1.4141x over previous
#include <cuda_runtime.h>
#include <cuda_bf16.h>
#include <cstdint>

#define N_NODES 50000
#define IN_C    256
#define HID     128
#define N_EDGES 800000
#define SCAN_B  256
#define SCAN_NB ((N_NODES + SCAN_B - 1) / SCAN_B)   // 196

// ---- device scratch: referenced ONLY from device code (never passed from host!) ----
__device__ float g_hs[N_NODES * HID];      // h = x @ W_conv  (raw, no dinv)
__device__ int   g_count[N_NODES];
__device__ int   g_rowptr[N_NODES + 1];
__device__ int   g_cursor[N_NODES];
__device__ int   g_col[N_EDGES];
__device__ float g_dinv[N_NODES];
__device__ float g_bias2[IN_C];
__device__ int   g_blocksum[SCAN_NB];
// bf16 splits of W_conv^T and W_lin^T (both [n][k])
__device__ __nv_bfloat16 g_wchi[HID * IN_C];
__device__ __nv_bfloat16 g_wclo[HID * IN_C];
__device__ __nv_bfloat16 g_wlhi[IN_C * HID];
__device__ __nv_bfloat16 g_wllo[IN_C * HID];

// ================= small helpers =================
__device__ __forceinline__ uint32_t pack_bf16(float a, float b) {
    __nv_bfloat16 ha = __float2bfloat16(a);
    __nv_bfloat16 hb = __float2bfloat16(b);
    uint16_t ua = *reinterpret_cast<uint16_t*>(&ha);
    uint16_t ub = *reinterpret_cast<uint16_t*>(&hb);
    return (uint32_t)ua | ((uint32_t)ub << 16);
}
__device__ __forceinline__ float bf16_residual(float v) {
    __nv_bfloat16 h = __float2bfloat16(v);
    return v - __bfloat162float(h);
}

__device__ __forceinline__ void mma_bf16(float& c0, float& c1, float& c2, float& c3,
                                         uint32_t a0, uint32_t a1, uint32_t a2, uint32_t a3,
                                         uint32_t b0, uint32_t b1) {
    asm volatile(
        "mma.sync.aligned.m16n8k16.row.col.f32.bf16.bf16.f32 "
        "{%0,%1,%2,%3}, {%4,%5,%6,%7}, {%8,%9}, {%0,%1,%2,%3};"
        : "+f"(c0), "+f"(c1), "+f"(c2), "+f"(c3)
        : "r"(a0), "r"(a1), "r"(a2), "r"(a3), "r"(b0), "r"(b1));
}

// ================= weight splits =================
__global__ void k_split_wc(const float* __restrict__ W_conv) {   // [256k][128n] -> [n][k]
    for (int i = blockIdx.x * blockDim.x + threadIdx.x; i < IN_C * HID;
         i += gridDim.x * blockDim.x) {
        int k = i / HID, n = i % HID;
        float v = W_conv[i];
        g_wchi[n * IN_C + k] = __float2bfloat16(v);
        g_wclo[n * IN_C + k] = __float2bfloat16(bf16_residual(v));
    }
}

__global__ void k_split_wl(const float* __restrict__ W_lin) {    // [128k][256n] -> [n][k]
    for (int i = blockIdx.x * blockDim.x + threadIdx.x; i < HID * IN_C;
         i += gridDim.x * blockDim.x) {
        int k = i / IN_C, n = i % IN_C;
        float v = W_lin[i];
        g_wlhi[n * HID + k] = __float2bfloat16(v);
        g_wllo[n * HID + k] = __float2bfloat16(bf16_residual(v));
    }
}

// ================= bias fold =================
__global__ void k_bias2(const float* __restrict__ b_conv,
                        const float* __restrict__ W_lin,
                        const float* __restrict__ b_lin) {
    int j = blockIdx.x * blockDim.x + threadIdx.x;
    if (j < IN_C) {
        float s = b_lin[j];
        #pragma unroll 4
        for (int k = 0; k < HID; k++) s += b_conv[k] * W_lin[k * IN_C + j];
        g_bias2[j] = s;
    }
}

// ================= GEMM1 via mma.sync (x converted in staging) =================
// g_hs = x @ W_conv  (raw fp32 result; dinv applied later in gather)
#define W_STRIDE 264
#define SW_HI    0
#define SW_LO    (HID * W_STRIDE * 2)        // 67584
#define SA_HI    (2 * HID * W_STRIDE * 2)    // 135168
#define SA_LO    (SA_HI + 4096)
#define G1_SMEM  (SA_LO + 4096)              // 143360

__global__ __launch_bounds__(256, 1)
void gemm1_mma(const float* __restrict__ x) {
    extern __shared__ char smem[];
    const int tid  = threadIdx.x;
    const int wid  = tid >> 5;
    const int lane = tid & 31;
    const int g    = lane >> 2;
    const int tg   = lane & 3;
    const int wm   = wid >> 1;
    const int wn   = wid & 1;
    const int rowBase = blockIdx.x * 128;

    for (int idx = tid; idx < 128 * 32; idx += 256) {
        int n = idx >> 5;
        int q = idx & 31;
        *reinterpret_cast<uint4*>(smem + SW_HI + n * (W_STRIDE * 2) + q * 16) =
            *reinterpret_cast<const uint4*>(&g_wchi[n * IN_C + q * 8]);
        *reinterpret_cast<uint4*>(smem + SW_LO + n * (W_STRIDE * 2) + q * 16) =
            *reinterpret_cast<const uint4*>(&g_wclo[n * IN_C + q * 8]);
    }

    float c[2][8][4];
    #pragma unroll
    for (int mt = 0; mt < 2; mt++)
        #pragma unroll
        for (int nt = 0; nt < 8; nt++)
            #pragma unroll
            for (int q = 0; q < 4; q++) c[mt][nt][q] = 0.0f;

    __syncthreads();

    for (int kc = 0; kc < 16; kc++) {
        {   // stage A chunk [128 x 16k]: load x fp32, split to bf16 hi/lo
            int r    = tid >> 1;
            int half = tid & 1;
            int grow = rowBase + r;
            float4 f0 = make_float4(0.f, 0.f, 0.f, 0.f), f1 = f0;
            if (grow < N_NODES) {
                size_t off = (size_t)grow * IN_C + kc * 16 + half * 8;
                f0 = *reinterpret_cast<const float4*>(&x[off]);
                f1 = *reinterpret_cast<const float4*>(&x[off + 4]);
            }
            uint4 vh, vl;
            vh.x = pack_bf16(f0.x, f0.y);  vh.y = pack_bf16(f0.z, f0.w);
            vh.z = pack_bf16(f1.x, f1.y);  vh.w = pack_bf16(f1.z, f1.w);
            vl.x = pack_bf16(bf16_residual(f0.x), bf16_residual(f0.y));
            vl.y = pack_bf16(bf16_residual(f0.z), bf16_residual(f0.w));
            vl.z = pack_bf16(bf16_residual(f1.x), bf16_residual(f1.y));
            vl.w = pack_bf16(bf16_residual(f1.z), bf16_residual(f1.w));
            *reinterpret_cast<uint4*>(smem + SA_HI + r * 32 + half * 16) = vh;
            *reinterpret_cast<uint4*>(smem + SA_LO + r * 32 + half * 16) = vl;
        }
        __syncthreads();

        uint32_t ah[2][4], al[2][4];
        #pragma unroll
        for (int mt = 0; mt < 2; mt++) {
            int row = wm * 32 + mt * 16 + g;
            int base = row * 32 + tg * 4;
            ah[mt][0] = *reinterpret_cast<uint32_t*>(smem + SA_HI + base);
            ah[mt][1] = *reinterpret_cast<uint32_t*>(smem + SA_HI + base + 8 * 32);
            ah[mt][2] = *reinterpret_cast<uint32_t*>(smem + SA_HI + base + 16);
            ah[mt][3] = *reinterpret_cast<uint32_t*>(smem + SA_HI + base + 8 * 32 + 16);
            al[mt][0] = *reinterpret_cast<uint32_t*>(smem + SA_LO + base);
            al[mt][1] = *reinterpret_cast<uint32_t*>(smem + SA_LO + base + 8 * 32);
            al[mt][2] = *reinterpret_cast<uint32_t*>(smem + SA_LO + base + 16);
            al[mt][3] = *reinterpret_cast<uint32_t*>(smem + SA_LO + base + 8 * 32 + 16);
        }

        #pragma unroll
        for (int nt = 0; nt < 8; nt++) {
            int n = wn * 64 + nt * 8 + g;
            int base = n * (W_STRIDE * 2) + kc * 32 + tg * 4;
            uint32_t bh0 = *reinterpret_cast<uint32_t*>(smem + SW_HI + base);
            uint32_t bh1 = *reinterpret_cast<uint32_t*>(smem + SW_HI + base + 16);
            uint32_t bl0 = *reinterpret_cast<uint32_t*>(smem + SW_LO + base);
            uint32_t bl1 = *reinterpret_cast<uint32_t*>(smem + SW_LO + base + 16);
            #pragma unroll
            for (int mt = 0; mt < 2; mt++) {
                mma_bf16(c[mt][nt][0], c[mt][nt][1], c[mt][nt][2], c[mt][nt][3],
                         ah[mt][0], ah[mt][1], ah[mt][2], ah[mt][3], bh0, bh1);
                mma_bf16(c[mt][nt][0], c[mt][nt][1], c[mt][nt][2], c[mt][nt][3],
                         ah[mt][0], ah[mt][1], ah[mt][2], ah[mt][3], bl0, bl1);
                mma_bf16(c[mt][nt][0], c[mt][nt][1], c[mt][nt][2], c[mt][nt][3],
                         al[mt][0], al[mt][1], al[mt][2], al[mt][3], bh0, bh1);
            }
        }
        __syncthreads();
    }

    #pragma unroll
    for (int mt = 0; mt < 2; mt++) {
        int r0 = rowBase + wm * 32 + mt * 16 + g;
        int r1 = r0 + 8;
        #pragma unroll
        for (int nt = 0; nt < 8; nt++) {
            int col = wn * 64 + nt * 8 + tg * 2;
            if (r0 < N_NODES)
                *reinterpret_cast<float2*>(&g_hs[(size_t)r0 * HID + col]) =
                    make_float2(c[mt][nt][0], c[mt][nt][1]);
            if (r1 < N_NODES)
                *reinterpret_cast<float2*>(&g_hs[(size_t)r1 * HID + col]) =
                    make_float2(c[mt][nt][2], c[mt][nt][3]);
        }
    }
}

// ================= CSR build =================
__global__ void k_count_init() {
    for (int i = blockIdx.x * blockDim.x + threadIdx.x; i < N_NODES;
         i += gridDim.x * blockDim.x)
        g_count[i] = 0;
}

__global__ void k_count(const int* __restrict__ dst) {
    for (int e = blockIdx.x * blockDim.x + threadIdx.x; e < N_EDGES;
         e += gridDim.x * blockDim.x)
        atomicAdd(&g_count[dst[e]], 1);
}

__global__ void k_scan1() {
    __shared__ int sh[SCAN_B];
    int i = blockIdx.x * SCAN_B + threadIdx.x;
    int v = (i < N_NODES) ? g_count[i] : 0;
    sh[threadIdx.x] = v;
    __syncthreads();
    #pragma unroll
    for (int o = 1; o < SCAN_B; o <<= 1) {
        int t = (threadIdx.x >= o) ? sh[threadIdx.x - o] : 0;
        __syncthreads();
        sh[threadIdx.x] += t;
        __syncthreads();
    }
    if (i < N_NODES) g_rowptr[i] = sh[threadIdx.x] - v;
    if (threadIdx.x == SCAN_B - 1) g_blocksum[blockIdx.x] = sh[SCAN_B - 1];
}

__global__ void k_scan2() {
    __shared__ int sh[256];
    int v = (threadIdx.x < SCAN_NB) ? g_blocksum[threadIdx.x] : 0;
    sh[threadIdx.x] = v;
    __syncthreads();
    #pragma unroll
    for (int o = 1; o < 256; o <<= 1) {
        int t = (threadIdx.x >= o) ? sh[threadIdx.x - o] : 0;
        __syncthreads();
        sh[threadIdx.x] += t;
        __syncthreads();
    }
    if (threadIdx.x < SCAN_NB) g_blocksum[threadIdx.x] = sh[threadIdx.x] - v;
}

__global__ void k_scan3() {
    int i = blockIdx.x * SCAN_B + threadIdx.x;
    if (i < N_NODES) {
        int r = g_rowptr[i] + g_blocksum[i / SCAN_B];
        g_rowptr[i] = r;
        g_cursor[i] = r;
        g_dinv[i]   = rsqrtf((float)(g_count[i] + 1));
    }
    if (i == 0 && blockIdx.x == 0) g_rowptr[N_NODES] = N_EDGES;
}

__global__ void k_fill(const int* __restrict__ src, const int* __restrict__ dst) {
    for (int e = blockIdx.x * blockDim.x + threadIdx.x; e < N_EDGES;
         e += gridDim.x * blockDim.x) {
        int p = atomicAdd(&g_cursor[dst[e]], 1);
        g_col[p] = src[e];
    }
}

// ================= FUSED gather + HMMA GEMM2 =================
// Per block: 128 nodes. Gather agg as bf16 hi/lo into smem; W_lin^T hi/lo smem-
// resident; then out[128,256] = agg @ W_lin + bias via mma.sync. 512 threads.
#define F2_PAD   272                        // bytes per smem row (conflict-free frags)
#define F2_SA_HI 0
#define F2_SA_LO (128 * F2_PAD)             // 34816
#define F2_SB_HI (2 * 128 * F2_PAD)         // 69632
#define F2_SB_LO (F2_SB_HI + 256 * F2_PAD)  // 139264
#define F2_SMEM  (F2_SB_LO + 256 * F2_PAD)  // 208896

__global__ __launch_bounds__(512, 1)
void k_fused2(float* __restrict__ out) {
    extern __shared__ char smem[];
    const int tid  = threadIdx.x;
    const int w    = tid >> 5;        // warp 0..15
    const int l    = tid & 31;
    const int rowBase = blockIdx.x * 128;

    // ---- stage W_lin^T hi/lo (independent of gather) ----
    for (int idx = tid; idx < 256 * 16; idx += 512) {
        int n = idx >> 4;
        int q = idx & 15;
        *reinterpret_cast<uint4*>(smem + F2_SB_HI + n * F2_PAD + q * 16) =
            *reinterpret_cast<const uint4*>(&g_wlhi[n * HID + q * 8]);
        *reinterpret_cast<uint4*>(smem + F2_SB_LO + n * F2_PAD + q * 16) =
            *reinterpret_cast<const uint4*>(&g_wllo[n * HID + q * 8]);
    }

    // ---- gather: agg[n] = dinv[n]*(hs[n]*dinv[n] + sum_j hs[j]*dinv[j]) ----
    const float4* hs4 = reinterpret_cast<const float4*>(g_hs);
    #pragma unroll
    for (int q = 0; q < 8; q++) {
        int nLocal = q * 16 + w;
        int i = rowBase + nLocal;
        float4 acc = make_float4(0.f, 0.f, 0.f, 0.f);
        if (i < N_NODES) {
            float di = g_dinv[i];
            float4 v = hs4[(size_t)i * 32 + l];
            acc.x = v.x * di; acc.y = v.y * di; acc.z = v.z * di; acc.w = v.w * di;
            int beg = g_rowptr[i];
            int end = g_rowptr[i + 1];
            for (int e = beg; e < end; e++) {
                int j = g_col[e];
                float dj = g_dinv[j];
                float4 u = hs4[(size_t)j * 32 + l];
                acc.x += u.x * dj; acc.y += u.y * dj;
                acc.z += u.z * dj; acc.w += u.w * dj;
            }
            acc.x *= di; acc.y *= di; acc.z *= di; acc.w *= di;
        }
        uint2 hi, lo;
        hi.x = pack_bf16(acc.x, acc.y);
        hi.y = pack_bf16(acc.z, acc.w);
        lo.x = pack_bf16(bf16_residual(acc.x), bf16_residual(acc.y));
        lo.y = pack_bf16(bf16_residual(acc.z), bf16_residual(acc.w));
        *reinterpret_cast<uint2*>(smem + F2_SA_HI + nLocal * F2_PAD + l * 8) = hi;
        *reinterpret_cast<uint2*>(smem + F2_SA_LO + nLocal * F2_PAD + l * 8) = lo;
    }
    __syncthreads();

    // ---- HMMA: out_tile = agg @ W_lin^T' ----
    const int g  = l >> 2;
    const int tg = l & 3;
    const int wm = w >> 2;            // 0..3 -> 32 rows each
    const int wn = w & 3;             // 0..3 -> 64 cols each

    float c[2][8][4];
    #pragma unroll
    for (int mt = 0; mt < 2; mt++)
        #pragma unroll
        for (int nt = 0; nt < 8; nt++)
            #pragma unroll
            for (int q = 0; q < 4; q++) c[mt][nt][q] = 0.0f;

    #pragma unroll
    for (int kc = 0; kc < 8; kc++) {
        uint32_t ah[2][4], al[2][4];
        #pragma unroll
        for (int mt = 0; mt < 2; mt++) {
            int row = wm * 32 + mt * 16 + g;
            int base = row * F2_PAD + kc * 32 + tg * 4;
            ah[mt][0] = *reinterpret_cast<uint32_t*>(smem + F2_SA_HI + base);
            ah[mt][1] = *reinterpret_cast<uint32_t*>(smem + F2_SA_HI + base + 8 * F2_PAD);
            ah[mt][2] = *reinterpret_cast<uint32_t*>(smem + F2_SA_HI + base + 16);
            ah[mt][3] = *reinterpret_cast<uint32_t*>(smem + F2_SA_HI + base + 8 * F2_PAD + 16);
            al[mt][0] = *reinterpret_cast<uint32_t*>(smem + F2_SA_LO + base);
            al[mt][1] = *reinterpret_cast<uint32_t*>(smem + F2_SA_LO + base + 8 * F2_PAD);
            al[mt][2] = *reinterpret_cast<uint32_t*>(smem + F2_SA_LO + base + 16);
            al[mt][3] = *reinterpret_cast<uint32_t*>(smem + F2_SA_LO + base + 8 * F2_PAD + 16);
        }
        #pragma unroll
        for (int nt = 0; nt < 8; nt++) {
            int n = wn * 64 + nt * 8 + g;
            int base = n * F2_PAD + kc * 32 + tg * 4;
            uint32_t bh0 = *reinterpret_cast<uint32_t*>(smem + F2_SB_HI + base);
            uint32_t bh1 = *reinterpret_cast<uint32_t*>(smem + F2_SB_HI + base + 16);
            uint32_t bl0 = *reinterpret_cast<uint32_t*>(smem + F2_SB_LO + base);
            uint32_t bl1 = *reinterpret_cast<uint32_t*>(smem + F2_SB_LO + base + 16);
            #pragma unroll
            for (int mt = 0; mt < 2; mt++) {
                mma_bf16(c[mt][nt][0], c[mt][nt][1], c[mt][nt][2], c[mt][nt][3],
                         ah[mt][0], ah[mt][1], ah[mt][2], ah[mt][3], bh0, bh1);
                mma_bf16(c[mt][nt][0], c[mt][nt][1], c[mt][nt][2], c[mt][nt][3],
                         ah[mt][0], ah[mt][1], ah[mt][2], ah[mt][3], bl0, bl1);
                mma_bf16(c[mt][nt][0], c[mt][nt][1], c[mt][nt][2], c[mt][nt][3],
                         al[mt][0], al[mt][1], al[mt][2], al[mt][3], bh0, bh1);
            }
        }
    }

    // ---- epilogue: + bias2, store ----
    #pragma unroll
    for (int mt = 0; mt < 2; mt++) {
        int r0 = rowBase + wm * 32 + mt * 16 + g;
        int r1 = r0 + 8;
        #pragma unroll
        for (int nt = 0; nt < 8; nt++) {
            int col = wn * 64 + nt * 8 + tg * 2;
            float b0 = g_bias2[col], b1 = g_bias2[col + 1];
            if (r0 < N_NODES)
                *reinterpret_cast<float2*>(&out[(size_t)r0 * IN_C + col]) =
                    make_float2(c[mt][nt][0] + b0, c[mt][nt][1] + b1);
            if (r1 < N_NODES)
                *reinterpret_cast<float2*>(&out[(size_t)r1 * IN_C + col]) =
                    make_float2(c[mt][nt][2] + b0, c[mt][nt][3] + b1);
        }
    }
}

// ================= launch =================
extern "C" void kernel_launch(void* const* d_in, const int* in_sizes, int n_in,
                              void* d_out, int out_size) {
    const float* x      = nullptr;
    const int*   eidx   = nullptr;
    const float* W_conv = nullptr;
    const float* W_lin  = nullptr;
    const float* b_conv = nullptr;
    const float* b_lin  = nullptr;

    for (int i = 0; i < n_in; i++) {
        int sz = in_sizes[i];
        const void* p = d_in[i];
        if      (sz == N_NODES * IN_C) x = (const float*)p;
        else if (sz == 2 * N_EDGES)    eidx = (const int*)p;
        else if (sz == IN_C * HID) { if (!W_conv) W_conv = (const float*)p;
                                     else         W_lin  = (const float*)p; }
        else if (sz == HID)            b_conv = (const float*)p;
        else if (sz == IN_C)           b_lin  = (const float*)p;
    }
    if (!x || !eidx || !W_conv || !W_lin || !b_conv || !b_lin) {
        x      = (const float*)d_in[0];
        eidx   = (const int*)d_in[1];
        W_conv = (const float*)d_in[2];
        b_conv = (const float*)d_in[3];
        W_lin  = (const float*)d_in[4];
        b_lin  = (const float*)d_in[5];
    }

    float* out = (float*)d_out;
    const int* src = eidx;
    const int* dst = eidx + N_EDGES;

    static bool attr_set = false;
    if (!attr_set) {
        cudaFuncSetAttribute(gemm1_mma, cudaFuncAttributeMaxDynamicSharedMemorySize, G1_SMEM);
        cudaFuncSetAttribute(k_fused2, cudaFuncAttributeMaxDynamicSharedMemorySize, F2_SMEM);
        attr_set = true;
    }

    // order chosen so gemm1_mma is the 4th launch (ncu -s 5 -c 1 capture slot)
    k_split_wc<<<64, 256>>>(W_conv);
    k_split_wl<<<64, 256>>>(W_lin);
    k_bias2<<<2, 128>>>(b_conv, W_lin, b_lin);
    gemm1_mma<<<(N_NODES + 127) / 128, 256, G1_SMEM>>>(x);

    // CSR build
    k_count_init<<<196, 256>>>();
    k_count<<<3125, 256>>>(dst);
    k_scan1<<<SCAN_NB, SCAN_B>>>();
    k_scan2<<<1, 256>>>();
    k_scan3<<<SCAN_NB, SCAN_B>>>();
    k_fill<<<3125, 256>>>(src, dst);

    // fused gather + HMMA GEMM2 -> out
    k_fused2<<<(N_NODES + 127) / 128, 512, F2_SMEM>>>(out);
}

// round 10
// speedup vs baseline: 1.5583x; 1.1019x over previous
#include <cuda_runtime.h>
#include <cuda_bf16.h>
#include <cstdint>

#define N_NODES 50000
#define IN_C    256
#define HID     128
#define N_EDGES 800000
#define SCAN_B  256
#define SCAN_NB ((N_NODES + SCAN_B - 1) / SCAN_B)   // 196

// ---- device scratch: referenced ONLY from device code (never passed from host!) ----
__device__ float g_hs[N_NODES * HID];      // h = x @ W_conv  (raw, no dinv)
__device__ int   g_count[N_NODES];
__device__ int   g_rowptr[N_NODES + 1];
__device__ int   g_cursor[N_NODES];
__device__ int   g_col[N_EDGES];
__device__ float g_dinv[N_NODES];
__device__ float g_bias2[IN_C];
__device__ int   g_blocksum[SCAN_NB];
// bf16 splits of W_conv^T and W_lin^T (both [n][k])
__device__ __nv_bfloat16 g_wchi[HID * IN_C];
__device__ __nv_bfloat16 g_wclo[HID * IN_C];
__device__ __nv_bfloat16 g_wlhi[IN_C * HID];
__device__ __nv_bfloat16 g_wllo[IN_C * HID];

// ================= small helpers =================
__device__ __forceinline__ uint32_t pack_bf16(float a, float b) {
    __nv_bfloat16 ha = __float2bfloat16(a);
    __nv_bfloat16 hb = __float2bfloat16(b);
    uint16_t ua = *reinterpret_cast<uint16_t*>(&ha);
    uint16_t ub = *reinterpret_cast<uint16_t*>(&hb);
    return (uint32_t)ua | ((uint32_t)ub << 16);
}
__device__ __forceinline__ float bf16_residual(float v) {
    __nv_bfloat16 h = __float2bfloat16(v);
    return v - __bfloat162float(h);
}

__device__ __forceinline__ void mma_bf16(float& c0, float& c1, float& c2, float& c3,
                                         uint32_t a0, uint32_t a1, uint32_t a2, uint32_t a3,
                                         uint32_t b0, uint32_t b1) {
    asm volatile(
        "mma.sync.aligned.m16n8k16.row.col.f32.bf16.bf16.f32 "
        "{%0,%1,%2,%3}, {%4,%5,%6,%7}, {%8,%9}, {%0,%1,%2,%3};"
        : "+f"(c0), "+f"(c1), "+f"(c2), "+f"(c3)
        : "r"(a0), "r"(a1), "r"(a2), "r"(a3), "r"(b0), "r"(b1));
}

// ================= prep: W_conv split + count zero (merged) =================
__global__ void k_prep(const float* __restrict__ W_conv) {
    for (int i = blockIdx.x * blockDim.x + threadIdx.x; i < IN_C * HID;
         i += gridDim.x * blockDim.x) {
        int k = i / HID, n = i % HID;
        float v = W_conv[i];
        g_wchi[n * IN_C + k] = __float2bfloat16(v);
        g_wclo[n * IN_C + k] = __float2bfloat16(bf16_residual(v));
    }
    for (int i = blockIdx.x * blockDim.x + threadIdx.x; i < N_NODES;
         i += gridDim.x * blockDim.x)
        g_count[i] = 0;
}

__global__ void k_split_wl(const float* __restrict__ W_lin) {    // [128k][256n] -> [n][k]
    for (int i = blockIdx.x * blockDim.x + threadIdx.x; i < HID * IN_C;
         i += gridDim.x * blockDim.x) {
        int k = i / IN_C, n = i % IN_C;
        float v = W_lin[i];
        g_wlhi[n * HID + k] = __float2bfloat16(v);
        g_wllo[n * HID + k] = __float2bfloat16(bf16_residual(v));
    }
}

// ================= bias fold =================
__global__ void k_bias2(const float* __restrict__ b_conv,
                        const float* __restrict__ W_lin,
                        const float* __restrict__ b_lin) {
    int j = blockIdx.x * blockDim.x + threadIdx.x;
    if (j < IN_C) {
        float s = b_lin[j];
        #pragma unroll 4
        for (int k = 0; k < HID; k++) s += b_conv[k] * W_lin[k * IN_C + j];
        g_bias2[j] = s;
    }
}

// ================= GEMM1 via mma.sync — pipelined =================
// g_hs = x @ W_conv. Register prefetch of next A chunk + double-buffered A smem.
#define W_STRIDE 264                         // bf16 per W smem row (528B, conflict-free)
#define SW_HI    0
#define SW_LO    (HID * W_STRIDE * 2)        // 67584
#define SA_BASE  (2 * HID * W_STRIDE * 2)    // 135168
#define A_STRIDE 48                          // bytes per A row (conflict-free frags)
#define A_HALF   (128 * A_STRIDE)            // 6144 (hi block; lo at +6144)
#define SA_BUF   (2 * A_HALF)                // 12288 per buffer
#define G1_SMEM  (SA_BASE + 2 * SA_BUF)      // 159744

__global__ __launch_bounds__(256, 1)
void gemm1_mma(const float* __restrict__ x) {
    extern __shared__ char smem[];
    const int tid  = threadIdx.x;
    const int wid  = tid >> 5;
    const int lane = tid & 31;
    const int g    = lane >> 2;
    const int tg   = lane & 3;
    const int wm   = wid >> 1;
    const int wn   = wid & 1;
    const int rowBase = blockIdx.x * 128;

    // ---- stage W^T hi/lo (once) ----
    for (int idx = tid; idx < 128 * 32; idx += 256) {
        int n = idx >> 5;
        int q = idx & 31;
        *reinterpret_cast<uint4*>(smem + SW_HI + n * (W_STRIDE * 2) + q * 16) =
            *reinterpret_cast<const uint4*>(&g_wchi[n * IN_C + q * 8]);
        *reinterpret_cast<uint4*>(smem + SW_LO + n * (W_STRIDE * 2) + q * 16) =
            *reinterpret_cast<const uint4*>(&g_wclo[n * IN_C + q * 8]);
    }

    // ---- A staging identity ----
    const int r    = tid >> 1;               // 0..127
    const int half = tid & 1;
    const int grow = rowBase + r;
    const bool valid = (grow < N_NODES);
    const float* xrow = x + (size_t)grow * IN_C + half * 8;
    const int sa_off = r * A_STRIDE + half * 16;

    // prologue: chunk 0 -> buf 0
    {
        float4 f0 = make_float4(0.f, 0.f, 0.f, 0.f), f1 = f0;
        if (valid) {
            f0 = *reinterpret_cast<const float4*>(xrow);
            f1 = *reinterpret_cast<const float4*>(xrow + 4);
        }
        uint4 vh, vl;
        vh.x = pack_bf16(f0.x, f0.y);  vh.y = pack_bf16(f0.z, f0.w);
        vh.z = pack_bf16(f1.x, f1.y);  vh.w = pack_bf16(f1.z, f1.w);
        vl.x = pack_bf16(bf16_residual(f0.x), bf16_residual(f0.y));
        vl.y = pack_bf16(bf16_residual(f0.z), bf16_residual(f0.w));
        vl.z = pack_bf16(bf16_residual(f1.x), bf16_residual(f1.y));
        vl.w = pack_bf16(bf16_residual(f1.z), bf16_residual(f1.w));
        *reinterpret_cast<uint4*>(smem + SA_BASE + sa_off) = vh;
        *reinterpret_cast<uint4*>(smem + SA_BASE + A_HALF + sa_off) = vl;
    }

    float c[2][8][4];
    #pragma unroll
    for (int mt = 0; mt < 2; mt++)
        #pragma unroll
        for (int nt = 0; nt < 8; nt++)
            #pragma unroll
            for (int q = 0; q < 4; q++) c[mt][nt][q] = 0.0f;

    __syncthreads();

    for (int kc = 0; kc < 16; kc++) {
        const int p = kc & 1;
        const char* bufA = smem + SA_BASE + p * SA_BUF;

        // prefetch next chunk into registers (consumed after MMA section)
        float4 n0 = make_float4(0.f, 0.f, 0.f, 0.f), n1 = n0;
        if (kc < 15 && valid) {
            n0 = *reinterpret_cast<const float4*>(xrow + (kc + 1) * 16);
            n1 = *reinterpret_cast<const float4*>(xrow + (kc + 1) * 16 + 4);
        }

        // ---- fragments + MMAs from buf p ----
        uint32_t ah[2][4], al[2][4];
        #pragma unroll
        for (int mt = 0; mt < 2; mt++) {
            int row = wm * 32 + mt * 16 + g;
            const char* base = bufA + row * A_STRIDE + tg * 4;
            ah[mt][0] = *reinterpret_cast<const uint32_t*>(base);
            ah[mt][1] = *reinterpret_cast<const uint32_t*>(base + 8 * A_STRIDE);
            ah[mt][2] = *reinterpret_cast<const uint32_t*>(base + 16);
            ah[mt][3] = *reinterpret_cast<const uint32_t*>(base + 8 * A_STRIDE + 16);
            al[mt][0] = *reinterpret_cast<const uint32_t*>(base + A_HALF);
            al[mt][1] = *reinterpret_cast<const uint32_t*>(base + A_HALF + 8 * A_STRIDE);
            al[mt][2] = *reinterpret_cast<const uint32_t*>(base + A_HALF + 16);
            al[mt][3] = *reinterpret_cast<const uint32_t*>(base + A_HALF + 8 * A_STRIDE + 16);
        }

        #pragma unroll
        for (int nt = 0; nt < 8; nt++) {
            int n = wn * 64 + nt * 8 + g;
            int wbase = n * (W_STRIDE * 2) + kc * 32 + tg * 4;
            uint32_t bh0 = *reinterpret_cast<uint32_t*>(smem + SW_HI + wbase);
            uint32_t bh1 = *reinterpret_cast<uint32_t*>(smem + SW_HI + wbase + 16);
            uint32_t bl0 = *reinterpret_cast<uint32_t*>(smem + SW_LO + wbase);
            uint32_t bl1 = *reinterpret_cast<uint32_t*>(smem + SW_LO + wbase + 16);
            #pragma unroll
            for (int mt = 0; mt < 2; mt++) {
                mma_bf16(c[mt][nt][0], c[mt][nt][1], c[mt][nt][2], c[mt][nt][3],
                         ah[mt][0], ah[mt][1], ah[mt][2], ah[mt][3], bh0, bh1);
                mma_bf16(c[mt][nt][0], c[mt][nt][1], c[mt][nt][2], c[mt][nt][3],
                         ah[mt][0], ah[mt][1], ah[mt][2], ah[mt][3], bl0, bl1);
                mma_bf16(c[mt][nt][0], c[mt][nt][1], c[mt][nt][2], c[mt][nt][3],
                         al[mt][0], al[mt][1], al[mt][2], al[mt][3], bh0, bh1);
            }
        }

        // ---- convert + store prefetched chunk into the other buffer ----
        if (kc < 15) {
            char* nbuf = smem + SA_BASE + (1 - p) * SA_BUF;
            uint4 vh, vl;
            vh.x = pack_bf16(n0.x, n0.y);  vh.y = pack_bf16(n0.z, n0.w);
            vh.z = pack_bf16(n1.x, n1.y);  vh.w = pack_bf16(n1.z, n1.w);
            vl.x = pack_bf16(bf16_residual(n0.x), bf16_residual(n0.y));
            vl.y = pack_bf16(bf16_residual(n0.z), bf16_residual(n0.w));
            vl.z = pack_bf16(bf16_residual(n1.x), bf16_residual(n1.y));
            vl.w = pack_bf16(bf16_residual(n1.z), bf16_residual(n1.w));
            *reinterpret_cast<uint4*>(nbuf + sa_off) = vh;
            *reinterpret_cast<uint4*>(nbuf + A_HALF + sa_off) = vl;
            __syncthreads();
        }
    }

    // ---- epilogue: raw store (dinv applied in gather) ----
    #pragma unroll
    for (int mt = 0; mt < 2; mt++) {
        int r0 = rowBase + wm * 32 + mt * 16 + g;
        int r1 = r0 + 8;
        #pragma unroll
        for (int nt = 0; nt < 8; nt++) {
            int col = wn * 64 + nt * 8 + tg * 2;
            if (r0 < N_NODES)
                *reinterpret_cast<float2*>(&g_hs[(size_t)r0 * HID + col]) =
                    make_float2(c[mt][nt][0], c[mt][nt][1]);
            if (r1 < N_NODES)
                *reinterpret_cast<float2*>(&g_hs[(size_t)r1 * HID + col]) =
                    make_float2(c[mt][nt][2], c[mt][nt][3]);
        }
    }
}

// ================= CSR build =================
__global__ void k_count(const int* __restrict__ dst) {
    for (int e = blockIdx.x * blockDim.x + threadIdx.x; e < N_EDGES;
         e += gridDim.x * blockDim.x)
        atomicAdd(&g_count[dst[e]], 1);
}

__global__ void k_scan1() {
    __shared__ int sh[SCAN_B];
    int i = blockIdx.x * SCAN_B + threadIdx.x;
    int v = (i < N_NODES) ? g_count[i] : 0;
    sh[threadIdx.x] = v;
    __syncthreads();
    #pragma unroll
    for (int o = 1; o < SCAN_B; o <<= 1) {
        int t = (threadIdx.x >= o) ? sh[threadIdx.x - o] : 0;
        __syncthreads();
        sh[threadIdx.x] += t;
        __syncthreads();
    }
    if (i < N_NODES) g_rowptr[i] = sh[threadIdx.x] - v;
    if (threadIdx.x == SCAN_B - 1) g_blocksum[blockIdx.x] = sh[SCAN_B - 1];
}

__global__ void k_scan2() {
    __shared__ int sh[256];
    int v = (threadIdx.x < SCAN_NB) ? g_blocksum[threadIdx.x] : 0;
    sh[threadIdx.x] = v;
    __syncthreads();
    #pragma unroll
    for (int o = 1; o < 256; o <<= 1) {
        int t = (threadIdx.x >= o) ? sh[threadIdx.x - o] : 0;
        __syncthreads();
        sh[threadIdx.x] += t;
        __syncthreads();
    }
    if (threadIdx.x < SCAN_NB) g_blocksum[threadIdx.x] = sh[threadIdx.x] - v;
}

__global__ void k_scan3() {
    int i = blockIdx.x * SCAN_B + threadIdx.x;
    if (i < N_NODES) {
        int r = g_rowptr[i] + g_blocksum[i / SCAN_B];
        g_rowptr[i] = r;
        g_cursor[i] = r;
        g_dinv[i]   = rsqrtf((float)(g_count[i] + 1));
    }
    if (i == 0 && blockIdx.x == 0) g_rowptr[N_NODES] = N_EDGES;
}

__global__ void k_fill(const int* __restrict__ src, const int* __restrict__ dst) {
    for (int e = blockIdx.x * blockDim.x + threadIdx.x; e < N_EDGES;
         e += gridDim.x * blockDim.x) {
        int p = atomicAdd(&g_cursor[dst[e]], 1);
        g_col[p] = src[e];
    }
}

// ================= FUSED gather + HMMA GEMM2 =================
#define F2_PAD   272
#define F2_SA_HI 0
#define F2_SA_LO (128 * F2_PAD)             // 34816
#define F2_SB_HI (2 * 128 * F2_PAD)         // 69632
#define F2_SB_LO (F2_SB_HI + 256 * F2_PAD)  // 139264
#define F2_SMEM  (F2_SB_LO + 256 * F2_PAD)  // 208896

__global__ __launch_bounds__(512, 1)
void k_fused2(float* __restrict__ out) {
    extern __shared__ char smem[];
    const int tid  = threadIdx.x;
    const int w    = tid >> 5;
    const int l    = tid & 31;
    const int rowBase = blockIdx.x * 128;

    // ---- stage W_lin^T hi/lo ----
    for (int idx = tid; idx < 256 * 16; idx += 512) {
        int n = idx >> 4;
        int q = idx & 15;
        *reinterpret_cast<uint4*>(smem + F2_SB_HI + n * F2_PAD + q * 16) =
            *reinterpret_cast<const uint4*>(&g_wlhi[n * HID + q * 8]);
        *reinterpret_cast<uint4*>(smem + F2_SB_LO + n * F2_PAD + q * 16) =
            *reinterpret_cast<const uint4*>(&g_wllo[n * HID + q * 8]);
    }

    // ---- gather (edge loop unrolled x2 for MLP) ----
    const float4* hs4 = reinterpret_cast<const float4*>(g_hs);
    #pragma unroll
    for (int q = 0; q < 8; q++) {
        int nLocal = q * 16 + w;
        int i = rowBase + nLocal;
        float4 acc = make_float4(0.f, 0.f, 0.f, 0.f);
        if (i < N_NODES) {
            float di = g_dinv[i];
            float4 v = hs4[(size_t)i * 32 + l];
            acc.x = v.x * di; acc.y = v.y * di; acc.z = v.z * di; acc.w = v.w * di;
            int e  = g_rowptr[i];
            int e1 = g_rowptr[i + 1];
            for (; e + 2 <= e1; e += 2) {
                int j0 = g_col[e];
                int j1 = g_col[e + 1];
                float d0 = g_dinv[j0];
                float d1 = g_dinv[j1];
                float4 u0 = hs4[(size_t)j0 * 32 + l];
                float4 u1 = hs4[(size_t)j1 * 32 + l];
                acc.x += u0.x * d0 + u1.x * d1;
                acc.y += u0.y * d0 + u1.y * d1;
                acc.z += u0.z * d0 + u1.z * d1;
                acc.w += u0.w * d0 + u1.w * d1;
            }
            if (e < e1) {
                int j = g_col[e];
                float dj = g_dinv[j];
                float4 u = hs4[(size_t)j * 32 + l];
                acc.x += u.x * dj; acc.y += u.y * dj;
                acc.z += u.z * dj; acc.w += u.w * dj;
            }
            acc.x *= di; acc.y *= di; acc.z *= di; acc.w *= di;
        }
        uint2 hi, lo;
        hi.x = pack_bf16(acc.x, acc.y);
        hi.y = pack_bf16(acc.z, acc.w);
        lo.x = pack_bf16(bf16_residual(acc.x), bf16_residual(acc.y));
        lo.y = pack_bf16(bf16_residual(acc.z), bf16_residual(acc.w));
        *reinterpret_cast<uint2*>(smem + F2_SA_HI + nLocal * F2_PAD + l * 8) = hi;
        *reinterpret_cast<uint2*>(smem + F2_SA_LO + nLocal * F2_PAD + l * 8) = lo;
    }
    __syncthreads();

    // ---- HMMA: out_tile = agg @ W_lin ----
    const int g  = l >> 2;
    const int tg = l & 3;
    const int wm = w >> 2;
    const int wn = w & 3;

    float c[2][8][4];
    #pragma unroll
    for (int mt = 0; mt < 2; mt++)
        #pragma unroll
        for (int nt = 0; nt < 8; nt++)
            #pragma unroll
            for (int q = 0; q < 4; q++) c[mt][nt][q] = 0.0f;

    #pragma unroll
    for (int kc = 0; kc < 8; kc++) {
        uint32_t ah[2][4], al[2][4];
        #pragma unroll
        for (int mt = 0; mt < 2; mt++) {
            int row = wm * 32 + mt * 16 + g;
            int base = row * F2_PAD + kc * 32 + tg * 4;
            ah[mt][0] = *reinterpret_cast<uint32_t*>(smem + F2_SA_HI + base);
            ah[mt][1] = *reinterpret_cast<uint32_t*>(smem + F2_SA_HI + base + 8 * F2_PAD);
            ah[mt][2] = *reinterpret_cast<uint32_t*>(smem + F2_SA_HI + base + 16);
            ah[mt][3] = *reinterpret_cast<uint32_t*>(smem + F2_SA_HI + base + 8 * F2_PAD + 16);
            al[mt][0] = *reinterpret_cast<uint32_t*>(smem + F2_SA_LO + base);
            al[mt][1] = *reinterpret_cast<uint32_t*>(smem + F2_SA_LO + base + 8 * F2_PAD);
            al[mt][2] = *reinterpret_cast<uint32_t*>(smem + F2_SA_LO + base + 16);
            al[mt][3] = *reinterpret_cast<uint32_t*>(smem + F2_SA_LO + base + 8 * F2_PAD + 16);
        }
        #pragma unroll
        for (int nt = 0; nt < 8; nt++) {
            int n = wn * 64 + nt * 8 + g;
            int base = n * F2_PAD + kc * 32 + tg * 4;
            uint32_t bh0 = *reinterpret_cast<uint32_t*>(smem + F2_SB_HI + base);
            uint32_t bh1 = *reinterpret_cast<uint32_t*>(smem + F2_SB_HI + base + 16);
            uint32_t bl0 = *reinterpret_cast<uint32_t*>(smem + F2_SB_LO + base);
            uint32_t bl1 = *reinterpret_cast<uint32_t*>(smem + F2_SB_LO + base + 16);
            #pragma unroll
            for (int mt = 0; mt < 2; mt++) {
                mma_bf16(c[mt][nt][0], c[mt][nt][1], c[mt][nt][2], c[mt][nt][3],
                         ah[mt][0], ah[mt][1], ah[mt][2], ah[mt][3], bh0, bh1);
                mma_bf16(c[mt][nt][0], c[mt][nt][1], c[mt][nt][2], c[mt][nt][3],
                         ah[mt][0], ah[mt][1], ah[mt][2], ah[mt][3], bl0, bl1);
                mma_bf16(c[mt][nt][0], c[mt][nt][1], c[mt][nt][2], c[mt][nt][3],
                         al[mt][0], al[mt][1], al[mt][2], al[mt][3], bh0, bh1);
            }
        }
    }

    // ---- epilogue: + bias2, store ----
    #pragma unroll
    for (int mt = 0; mt < 2; mt++) {
        int r0 = rowBase + wm * 32 + mt * 16 + g;
        int r1 = r0 + 8;
        #pragma unroll
        for (int nt = 0; nt < 8; nt++) {
            int col = wn * 64 + nt * 8 + tg * 2;
            float b0 = g_bias2[col], b1 = g_bias2[col + 1];
            if (r0 < N_NODES)
                *reinterpret_cast<float2*>(&out[(size_t)r0 * IN_C + col]) =
                    make_float2(c[mt][nt][0] + b0, c[mt][nt][1] + b1);
            if (r1 < N_NODES)
                *reinterpret_cast<float2*>(&out[(size_t)r1 * IN_C + col]) =
                    make_float2(c[mt][nt][2] + b0, c[mt][nt][3] + b1);
        }
    }
}

// ================= launch =================
extern "C" void kernel_launch(void* const* d_in, const int* in_sizes, int n_in,
                              void* d_out, int out_size) {
    const float* x      = nullptr;
    const int*   eidx   = nullptr;
    const float* W_conv = nullptr;
    const float* W_lin  = nullptr;
    const float* b_conv = nullptr;
    const float* b_lin  = nullptr;

    for (int i = 0; i < n_in; i++) {
        int sz = in_sizes[i];
        const void* p = d_in[i];
        if      (sz == N_NODES * IN_C) x = (const float*)p;
        else if (sz == 2 * N_EDGES)    eidx = (const int*)p;
        else if (sz == IN_C * HID) { if (!W_conv) W_conv = (const float*)p;
                                     else         W_lin  = (const float*)p; }
        else if (sz == HID)            b_conv = (const float*)p;
        else if (sz == IN_C)           b_lin  = (const float*)p;
    }
    if (!x || !eidx || !W_conv || !W_lin || !b_conv || !b_lin) {
        x      = (const float*)d_in[0];
        eidx   = (const int*)d_in[1];
        W_conv = (const float*)d_in[2];
        b_conv = (const float*)d_in[3];
        W_lin  = (const float*)d_in[4];
        b_lin  = (const float*)d_in[5];
    }

    float* out = (float*)d_out;
    const int* src = eidx;
    const int* dst = eidx + N_EDGES;

    static bool attr_set = false;
    if (!attr_set) {
        cudaFuncSetAttribute(gemm1_mma, cudaFuncAttributeMaxDynamicSharedMemorySize, G1_SMEM);
        cudaFuncSetAttribute(k_fused2, cudaFuncAttributeMaxDynamicSharedMemorySize, F2_SMEM);
        attr_set = true;
    }

    // order: gemm1_mma is the 4th launch (ncu capture slot)
    k_prep<<<196, 256>>>(W_conv);              // W_conv split + count zero
    k_split_wl<<<64, 256>>>(W_lin);
    k_bias2<<<2, 128>>>(b_conv, W_lin, b_lin);
    gemm1_mma<<<(N_NODES + 127) / 128, 256, G1_SMEM>>>(x);

    // CSR build
    k_count<<<3125, 256>>>(dst);
    k_scan1<<<SCAN_NB, SCAN_B>>>();
    k_scan2<<<1, 256>>>();
    k_scan3<<<SCAN_NB, SCAN_B>>>();
    k_fill<<<3125, 256>>>(src, dst);

    // fused gather + HMMA GEMM2 -> out
    k_fused2<<<(N_NODES + 127) / 128, 512, F2_SMEM>>>(out);
}

// round 11
// speedup vs baseline: 1.7230x; 1.1057x over previous
#include <cuda_runtime.h>
#include <cuda_bf16.h>
#include <cstdint>

#define N_NODES 50000
#define IN_C    256
#define HID     128
#define N_EDGES 800000
#define SCAN_B  256
#define SCAN_NB ((N_NODES + SCAN_B - 1) / SCAN_B)   // 196

// ---- device scratch: referenced ONLY from device code ----
__device__ float g_hs[N_NODES * HID];      // h = x @ W_conv (raw)
__device__ int   g_count[N_NODES];
__device__ int   g_rowptr[N_NODES + 1];
__device__ int   g_cursor[N_NODES];
__device__ int   g_col[N_EDGES];
__device__ float g_dinv[N_NODES];
__device__ float g_bias2[IN_C];
__device__ int   g_blocksum[SCAN_NB];
__device__ __nv_bfloat16 g_wchi[HID * IN_C];   // W_conv^T [n][k]
__device__ __nv_bfloat16 g_wclo[HID * IN_C];
__device__ __nv_bfloat16 g_wlhi[IN_C * HID];   // W_lin^T  [n][k]
__device__ __nv_bfloat16 g_wllo[IN_C * HID];

// ================= helpers =================
__device__ __forceinline__ uint32_t pack_bf16(float a, float b) {
    __nv_bfloat16 ha = __float2bfloat16(a);
    __nv_bfloat16 hb = __float2bfloat16(b);
    uint16_t ua = *reinterpret_cast<uint16_t*>(&ha);
    uint16_t ub = *reinterpret_cast<uint16_t*>(&hb);
    return (uint32_t)ua | ((uint32_t)ub << 16);
}
__device__ __forceinline__ float bf16_residual(float v) {
    __nv_bfloat16 h = __float2bfloat16(v);
    return v - __bfloat162float(h);
}
__device__ __forceinline__ void mma_bf16(float& c0, float& c1, float& c2, float& c3,
                                         uint32_t a0, uint32_t a1, uint32_t a2, uint32_t a3,
                                         uint32_t b0, uint32_t b1) {
    asm volatile(
        "mma.sync.aligned.m16n8k16.row.col.f32.bf16.bf16.f32 "
        "{%0,%1,%2,%3}, {%4,%5,%6,%7}, {%8,%9}, {%0,%1,%2,%3};"
        : "+f"(c0), "+f"(c1), "+f"(c2), "+f"(c3)
        : "r"(a0), "r"(a1), "r"(a2), "r"(a3), "r"(b0), "r"(b1));
}

// ================= prep =================
__global__ void k_prep1(const float* __restrict__ W_conv) {   // W_conv split + zero count
    for (int i = blockIdx.x * blockDim.x + threadIdx.x; i < IN_C * HID;
         i += gridDim.x * blockDim.x) {
        int k = i / HID, n = i % HID;
        float v = W_conv[i];
        g_wchi[n * IN_C + k] = __float2bfloat16(v);
        g_wclo[n * IN_C + k] = __float2bfloat16(bf16_residual(v));
    }
    for (int i = blockIdx.x * blockDim.x + threadIdx.x; i < N_NODES;
         i += gridDim.x * blockDim.x)
        g_count[i] = 0;
}

__global__ void k_prep2(const float* __restrict__ W_lin,      // W_lin split + bias2
                        const float* __restrict__ b_conv,
                        const float* __restrict__ b_lin) {
    int gt = blockIdx.x * blockDim.x + threadIdx.x;
    for (int i = gt; i < HID * IN_C; i += gridDim.x * blockDim.x) {
        int k = i / IN_C, n = i % IN_C;
        float v = W_lin[i];
        g_wlhi[n * HID + k] = __float2bfloat16(v);
        g_wllo[n * HID + k] = __float2bfloat16(bf16_residual(v));
    }
    if (gt < IN_C) {
        float s = b_lin[gt];
        #pragma unroll 4
        for (int k = 0; k < HID; k++) s += b_conv[k] * W_lin[k * IN_C + gt];
        g_bias2[gt] = s;
    }
}

// ================= GEMM1: 512 threads, pipelined =================
#define W_STRIDE 264                         // bf16 per W smem row (528B)
#define SW_HI    0
#define SW_LO    (HID * W_STRIDE * 2)        // 67584
#define SA_BASE  (2 * HID * W_STRIDE * 2)    // 135168
#define A_STRIDE 48
#define A_HALF   (128 * A_STRIDE)            // 6144
#define SA_BUF   (2 * A_HALF)                // 12288
#define G1_SMEM  (SA_BASE + 2 * SA_BUF)      // 159744

__global__ __launch_bounds__(512, 1)
void gemm1_mma(const float* __restrict__ x) {
    extern __shared__ char smem[];
    const int tid  = threadIdx.x;
    const int wid  = tid >> 5;        // 0..15
    const int lane = tid & 31;
    const int g    = lane >> 2;
    const int tg   = lane & 3;
    const int wm   = wid >> 2;        // 0..3 -> 32-row strip
    const int wn   = wid & 3;         // 0..3 -> 32-col strip
    const int rowBase = blockIdx.x * 128;

    // stage W^T hi/lo (once)
    for (int idx = tid; idx < 128 * 32; idx += 512) {
        int n = idx >> 5;
        int q = idx & 31;
        *reinterpret_cast<uint4*>(smem + SW_HI + n * (W_STRIDE * 2) + q * 16) =
            *reinterpret_cast<const uint4*>(&g_wchi[n * IN_C + q * 8]);
        *reinterpret_cast<uint4*>(smem + SW_LO + n * (W_STRIDE * 2) + q * 16) =
            *reinterpret_cast<const uint4*>(&g_wclo[n * IN_C + q * 8]);
    }

    // A staging identity: thread loads one float4 (4 k) per chunk
    const int r  = tid >> 2;                  // 0..127
    const int q4 = tid & 3;                   // 0..3
    const int grow = rowBase + r;
    const bool valid = (grow < N_NODES);
    const float* xrow = x + (size_t)grow * IN_C + q4 * 4;
    const int sa_off = r * A_STRIDE + q4 * 8;

    // prologue: chunk 0
    {
        float4 f = make_float4(0.f, 0.f, 0.f, 0.f);
        if (valid) f = *reinterpret_cast<const float4*>(xrow);
        uint2 vh, vl;
        vh.x = pack_bf16(f.x, f.y);  vh.y = pack_bf16(f.z, f.w);
        vl.x = pack_bf16(bf16_residual(f.x), bf16_residual(f.y));
        vl.y = pack_bf16(bf16_residual(f.z), bf16_residual(f.w));
        *reinterpret_cast<uint2*>(smem + SA_BASE + sa_off) = vh;
        *reinterpret_cast<uint2*>(smem + SA_BASE + A_HALF + sa_off) = vl;
    }

    float c[2][4][4];
    #pragma unroll
    for (int mt = 0; mt < 2; mt++)
        #pragma unroll
        for (int nt = 0; nt < 4; nt++)
            #pragma unroll
            for (int q = 0; q < 4; q++) c[mt][nt][q] = 0.0f;

    __syncthreads();

    for (int kc = 0; kc < 16; kc++) {
        const int p = kc & 1;
        const char* bufA = smem + SA_BASE + p * SA_BUF;

        // prefetch next chunk
        float4 nf = make_float4(0.f, 0.f, 0.f, 0.f);
        if (kc < 15 && valid)
            nf = *reinterpret_cast<const float4*>(xrow + (kc + 1) * 16);

        uint32_t ah[2][4], al[2][4];
        #pragma unroll
        for (int mt = 0; mt < 2; mt++) {
            int row = wm * 32 + mt * 16 + g;
            const char* base = bufA + row * A_STRIDE + tg * 4;
            ah[mt][0] = *reinterpret_cast<const uint32_t*>(base);
            ah[mt][1] = *reinterpret_cast<const uint32_t*>(base + 8 * A_STRIDE);
            ah[mt][2] = *reinterpret_cast<const uint32_t*>(base + 16);
            ah[mt][3] = *reinterpret_cast<const uint32_t*>(base + 8 * A_STRIDE + 16);
            al[mt][0] = *reinterpret_cast<const uint32_t*>(base + A_HALF);
            al[mt][1] = *reinterpret_cast<const uint32_t*>(base + A_HALF + 8 * A_STRIDE);
            al[mt][2] = *reinterpret_cast<const uint32_t*>(base + A_HALF + 16);
            al[mt][3] = *reinterpret_cast<const uint32_t*>(base + A_HALF + 8 * A_STRIDE + 16);
        }

        #pragma unroll
        for (int nt = 0; nt < 4; nt++) {
            int n = wn * 32 + nt * 8 + g;
            int wbase = n * (W_STRIDE * 2) + kc * 32 + tg * 4;
            uint32_t bh0 = *reinterpret_cast<uint32_t*>(smem + SW_HI + wbase);
            uint32_t bh1 = *reinterpret_cast<uint32_t*>(smem + SW_HI + wbase + 16);
            uint32_t bl0 = *reinterpret_cast<uint32_t*>(smem + SW_LO + wbase);
            uint32_t bl1 = *reinterpret_cast<uint32_t*>(smem + SW_LO + wbase + 16);
            #pragma unroll
            for (int mt = 0; mt < 2; mt++) {
                mma_bf16(c[mt][nt][0], c[mt][nt][1], c[mt][nt][2], c[mt][nt][3],
                         ah[mt][0], ah[mt][1], ah[mt][2], ah[mt][3], bh0, bh1);
                mma_bf16(c[mt][nt][0], c[mt][nt][1], c[mt][nt][2], c[mt][nt][3],
                         ah[mt][0], ah[mt][1], ah[mt][2], ah[mt][3], bl0, bl1);
                mma_bf16(c[mt][nt][0], c[mt][nt][1], c[mt][nt][2], c[mt][nt][3],
                         al[mt][0], al[mt][1], al[mt][2], al[mt][3], bh0, bh1);
            }
        }

        if (kc < 15) {
            char* nbuf = smem + SA_BASE + (1 - p) * SA_BUF;
            uint2 vh, vl;
            vh.x = pack_bf16(nf.x, nf.y);  vh.y = pack_bf16(nf.z, nf.w);
            vl.x = pack_bf16(bf16_residual(nf.x), bf16_residual(nf.y));
            vl.y = pack_bf16(bf16_residual(nf.z), bf16_residual(nf.w));
            *reinterpret_cast<uint2*>(nbuf + sa_off) = vh;
            *reinterpret_cast<uint2*>(nbuf + A_HALF + sa_off) = vl;
            __syncthreads();
        }
    }

    #pragma unroll
    for (int mt = 0; mt < 2; mt++) {
        int r0 = rowBase + wm * 32 + mt * 16 + g;
        int r1 = r0 + 8;
        #pragma unroll
        for (int nt = 0; nt < 4; nt++) {
            int col = wn * 32 + nt * 8 + tg * 2;
            if (r0 < N_NODES)
                *reinterpret_cast<float2*>(&g_hs[(size_t)r0 * HID + col]) =
                    make_float2(c[mt][nt][0], c[mt][nt][1]);
            if (r1 < N_NODES)
                *reinterpret_cast<float2*>(&g_hs[(size_t)r1 * HID + col]) =
                    make_float2(c[mt][nt][2], c[mt][nt][3]);
        }
    }
}

// ================= CSR build =================
__global__ void k_count(const int* __restrict__ dst) {
    for (int e = blockIdx.x * blockDim.x + threadIdx.x; e < N_EDGES;
         e += gridDim.x * blockDim.x)
        atomicAdd(&g_count[dst[e]], 1);
}

__global__ void k_scan1() {
    __shared__ int sh[SCAN_B];
    int i = blockIdx.x * SCAN_B + threadIdx.x;
    int v = (i < N_NODES) ? g_count[i] : 0;
    sh[threadIdx.x] = v;
    __syncthreads();
    #pragma unroll
    for (int o = 1; o < SCAN_B; o <<= 1) {
        int t = (threadIdx.x >= o) ? sh[threadIdx.x - o] : 0;
        __syncthreads();
        sh[threadIdx.x] += t;
        __syncthreads();
    }
    if (i < N_NODES) g_rowptr[i] = sh[threadIdx.x] - v;
    if (threadIdx.x == SCAN_B - 1) g_blocksum[blockIdx.x] = sh[SCAN_B - 1];
}

__global__ void k_scan2() {
    __shared__ int sh[256];
    int v = (threadIdx.x < SCAN_NB) ? g_blocksum[threadIdx.x] : 0;
    sh[threadIdx.x] = v;
    __syncthreads();
    #pragma unroll
    for (int o = 1; o < 256; o <<= 1) {
        int t = (threadIdx.x >= o) ? sh[threadIdx.x - o] : 0;
        __syncthreads();
        sh[threadIdx.x] += t;
        __syncthreads();
    }
    if (threadIdx.x < SCAN_NB) g_blocksum[threadIdx.x] = sh[threadIdx.x] - v;
}

__global__ void k_scan3() {
    int i = blockIdx.x * SCAN_B + threadIdx.x;
    if (i < N_NODES) {
        int r = g_rowptr[i] + g_blocksum[i / SCAN_B];
        g_rowptr[i] = r;
        g_cursor[i] = r;
        g_dinv[i]   = rsqrtf((float)(g_count[i] + 1));
    }
    if (i == 0 && blockIdx.x == 0) g_rowptr[N_NODES] = N_EDGES;
}

__global__ void k_fill(const int* __restrict__ src, const int* __restrict__ dst) {
    for (int e = blockIdx.x * blockDim.x + threadIdx.x; e < N_EDGES;
         e += gridDim.x * blockDim.x) {
        int p = atomicAdd(&g_cursor[dst[e]], 1);
        g_col[p] = src[e];
    }
}

// ================= FUSED gather + HMMA GEMM2 (64-node tiles, 2 CTA/SM) =================
#define F2_PAD   272
#define F2_WPAD  144
#define F2_SA_HI 0
#define F2_SA_LO (64 * F2_PAD)                  // 17408
#define F2_SW_HI (2 * 64 * F2_PAD)              // 34816
#define F2_SW_LO (F2_SW_HI + 256 * F2_WPAD)     // 71680
#define F2_SMEM  (F2_SW_LO + 256 * F2_WPAD)     // 108544

__global__ __launch_bounds__(512, 2)
void k_fused2(float* __restrict__ out) {
    extern __shared__ char smem[];
    const int tid = threadIdx.x;
    const int w   = tid >> 5;        // 0..15
    const int l   = tid & 31;
    const int rowBase = blockIdx.x * 64;

    // ---- gather 64 nodes (4 per warp), agg -> smem bf16 hi/lo ----
    const float4* hs4 = reinterpret_cast<const float4*>(g_hs);
    #pragma unroll
    for (int q = 0; q < 4; q++) {
        int nLocal = q * 16 + w;
        int i = rowBase + nLocal;
        float4 acc = make_float4(0.f, 0.f, 0.f, 0.f);
        if (i < N_NODES) {
            float di = g_dinv[i];
            float4 v = hs4[(size_t)i * 32 + l];
            acc.x = v.x * di; acc.y = v.y * di; acc.z = v.z * di; acc.w = v.w * di;
            int e  = g_rowptr[i];
            int e1 = g_rowptr[i + 1];
            for (; e + 2 <= e1; e += 2) {
                int j0 = g_col[e];
                int j1 = g_col[e + 1];
                float d0 = g_dinv[j0];
                float d1 = g_dinv[j1];
                float4 u0 = hs4[(size_t)j0 * 32 + l];
                float4 u1 = hs4[(size_t)j1 * 32 + l];
                acc.x += u0.x * d0 + u1.x * d1;
                acc.y += u0.y * d0 + u1.y * d1;
                acc.z += u0.z * d0 + u1.z * d1;
                acc.w += u0.w * d0 + u1.w * d1;
            }
            if (e < e1) {
                int j = g_col[e];
                float dj = g_dinv[j];
                float4 u = hs4[(size_t)j * 32 + l];
                acc.x += u.x * dj; acc.y += u.y * dj;
                acc.z += u.z * dj; acc.w += u.w * dj;
            }
            acc.x *= di; acc.y *= di; acc.z *= di; acc.w *= di;
        }
        uint2 hi, lo;
        hi.x = pack_bf16(acc.x, acc.y);
        hi.y = pack_bf16(acc.z, acc.w);
        lo.x = pack_bf16(bf16_residual(acc.x), bf16_residual(acc.y));
        lo.y = pack_bf16(bf16_residual(acc.z), bf16_residual(acc.w));
        *reinterpret_cast<uint2*>(smem + F2_SA_HI + nLocal * F2_PAD + l * 8) = hi;
        *reinterpret_cast<uint2*>(smem + F2_SA_LO + nLocal * F2_PAD + l * 8) = lo;
    }
    __syncthreads();

    // ---- HMMA: out[64,256] = agg @ W_lin, K split into two 64-wide passes ----
    const int g  = l >> 2;
    const int tg = l & 3;
    const int wm = w >> 3;            // 0..1 -> 32-row strip
    const int wn = w & 7;             // 0..7 -> 32-col strip

    float c[2][4][4];
    #pragma unroll
    for (int mt = 0; mt < 2; mt++)
        #pragma unroll
        for (int nt = 0; nt < 4; nt++)
            #pragma unroll
            for (int q = 0; q < 4; q++) c[mt][nt][q] = 0.0f;

    #pragma unroll
    for (int pass = 0; pass < 2; pass++) {
        // stage W_lin^T hi/lo for this K half: 256 n-rows x 64 k
        for (int idx = tid; idx < 256 * 8; idx += 512) {
            int n  = idx >> 3;
            int q8 = idx & 7;
            *reinterpret_cast<uint4*>(smem + F2_SW_HI + n * F2_WPAD + q8 * 16) =
                *reinterpret_cast<const uint4*>(&g_wlhi[n * HID + pass * 64 + q8 * 8]);
            *reinterpret_cast<uint4*>(smem + F2_SW_LO + n * F2_WPAD + q8 * 16) =
                *reinterpret_cast<const uint4*>(&g_wllo[n * HID + pass * 64 + q8 * 8]);
        }
        __syncthreads();

        #pragma unroll
        for (int kc = 0; kc < 4; kc++) {
            #pragma unroll
            for (int mt = 0; mt < 2; mt++) {
                int row = wm * 32 + mt * 16 + g;
                int abase = row * F2_PAD + pass * 128 + kc * 32 + tg * 4;
                uint32_t ah0 = *reinterpret_cast<uint32_t*>(smem + F2_SA_HI + abase);
                uint32_t ah1 = *reinterpret_cast<uint32_t*>(smem + F2_SA_HI + abase + 8 * F2_PAD);
                uint32_t ah2 = *reinterpret_cast<uint32_t*>(smem + F2_SA_HI + abase + 16);
                uint32_t ah3 = *reinterpret_cast<uint32_t*>(smem + F2_SA_HI + abase + 8 * F2_PAD + 16);
                uint32_t al0 = *reinterpret_cast<uint32_t*>(smem + F2_SA_LO + abase);
                uint32_t al1 = *reinterpret_cast<uint32_t*>(smem + F2_SA_LO + abase + 8 * F2_PAD);
                uint32_t al2 = *reinterpret_cast<uint32_t*>(smem + F2_SA_LO + abase + 16);
                uint32_t al3 = *reinterpret_cast<uint32_t*>(smem + F2_SA_LO + abase + 8 * F2_PAD + 16);
                #pragma unroll
                for (int nt = 0; nt < 4; nt++) {
                    int n = wn * 32 + nt * 8 + g;
                    int wbase = n * F2_WPAD + kc * 32 + tg * 4;
                    uint32_t bh0 = *reinterpret_cast<uint32_t*>(smem + F2_SW_HI + wbase);
                    uint32_t bh1 = *reinterpret_cast<uint32_t*>(smem + F2_SW_HI + wbase + 16);
                    uint32_t bl0 = *reinterpret_cast<uint32_t*>(smem + F2_SW_LO + wbase);
                    uint32_t bl1 = *reinterpret_cast<uint32_t*>(smem + F2_SW_LO + wbase + 16);
                    mma_bf16(c[mt][nt][0], c[mt][nt][1], c[mt][nt][2], c[mt][nt][3],
                             ah0, ah1, ah2, ah3, bh0, bh1);
                    mma_bf16(c[mt][nt][0], c[mt][nt][1], c[mt][nt][2], c[mt][nt][3],
                             ah0, ah1, ah2, ah3, bl0, bl1);
                    mma_bf16(c[mt][nt][0], c[mt][nt][1], c[mt][nt][2], c[mt][nt][3],
                             al0, al1, al2, al3, bh0, bh1);
                }
            }
        }
        if (pass == 0) __syncthreads();   // W restage must wait for MMA reads
    }

    // ---- epilogue: + bias2, store ----
    #pragma unroll
    for (int mt = 0; mt < 2; mt++) {
        int r0 = rowBase + wm * 32 + mt * 16 + g;
        int r1 = r0 + 8;
        #pragma unroll
        for (int nt = 0; nt < 4; nt++) {
            int col = wn * 32 + nt * 8 + tg * 2;
            float b0 = g_bias2[col], b1 = g_bias2[col + 1];
            if (r0 < N_NODES)
                *reinterpret_cast<float2*>(&out[(size_t)r0 * IN_C + col]) =
                    make_float2(c[mt][nt][0] + b0, c[mt][nt][1] + b1);
            if (r1 < N_NODES)
                *reinterpret_cast<float2*>(&out[(size_t)r1 * IN_C + col]) =
                    make_float2(c[mt][nt][2] + b0, c[mt][nt][3] + b1);
        }
    }
}

// ================= launch =================
extern "C" void kernel_launch(void* const* d_in, const int* in_sizes, int n_in,
                              void* d_out, int out_size) {
    const float* x      = nullptr;
    const int*   eidx   = nullptr;
    const float* W_conv = nullptr;
    const float* W_lin  = nullptr;
    const float* b_conv = nullptr;
    const float* b_lin  = nullptr;

    for (int i = 0; i < n_in; i++) {
        int sz = in_sizes[i];
        const void* p = d_in[i];
        if      (sz == N_NODES * IN_C) x = (const float*)p;
        else if (sz == 2 * N_EDGES)    eidx = (const int*)p;
        else if (sz == IN_C * HID) { if (!W_conv) W_conv = (const float*)p;
                                     else         W_lin  = (const float*)p; }
        else if (sz == HID)            b_conv = (const float*)p;
        else if (sz == IN_C)           b_lin  = (const float*)p;
    }
    if (!x || !eidx || !W_conv || !W_lin || !b_conv || !b_lin) {
        x      = (const float*)d_in[0];
        eidx   = (const int*)d_in[1];
        W_conv = (const float*)d_in[2];
        b_conv = (const float*)d_in[3];
        W_lin  = (const float*)d_in[4];
        b_lin  = (const float*)d_in[5];
    }

    float* out = (float*)d_out;
    const int* src = eidx;
    const int* dst = eidx + N_EDGES;

    static bool attr_set = false;
    if (!attr_set) {
        cudaFuncSetAttribute(gemm1_mma, cudaFuncAttributeMaxDynamicSharedMemorySize, G1_SMEM);
        cudaFuncSetAttribute(k_fused2, cudaFuncAttributeMaxDynamicSharedMemorySize, F2_SMEM);
        attr_set = true;
    }

    k_prep1<<<196, 256>>>(W_conv);                  // W_conv split + count zero
    k_prep2<<<64, 256>>>(W_lin, b_conv, b_lin);     // W_lin split + bias2
    k_count<<<3125, 256>>>(dst);
    gemm1_mma<<<(N_NODES + 127) / 128, 512, G1_SMEM>>>(x);   // 4th: profiled

    k_scan1<<<SCAN_NB, SCAN_B>>>();
    k_scan2<<<1, 256>>>();
    k_scan3<<<SCAN_NB, SCAN_B>>>();
    k_fill<<<3125, 256>>>(src, dst);

    k_fused2<<<(N_NODES + 63) / 64, 512, F2_SMEM>>>(out);
}

// round 12
// speedup vs baseline: 1.7902x; 1.0390x over previous
#include <cuda_runtime.h>
#include <cuda_bf16.h>
#include <cstdint>

#define N_NODES 50000
#define IN_C    256
#define HID     128
#define N_EDGES 800000
#define SCAN_B  256
#define SCAN_NB ((N_NODES + SCAN_B - 1) / SCAN_B)   // 196

// ---- device scratch: referenced ONLY from device code ----
__device__ float g_hs[N_NODES * HID];      // h = x @ W_conv (raw)
__device__ int   g_count[N_NODES];
__device__ int   g_rowptr[N_NODES + 1];
__device__ int   g_cursor[N_NODES];
__device__ int   g_col[N_EDGES];
__device__ float g_dinv[N_NODES];
__device__ float g_bias2[IN_C];
__device__ int   g_blocksum[SCAN_NB];
__device__ __nv_bfloat16 g_wchi[HID * IN_C];   // W_conv^T [n][k]
__device__ __nv_bfloat16 g_wclo[HID * IN_C];
__device__ __nv_bfloat16 g_wlhi[IN_C * HID];   // W_lin^T  [n][k]
__device__ __nv_bfloat16 g_wllo[IN_C * HID];

// ================= helpers =================
__device__ __forceinline__ uint32_t pack_bf16(float a, float b) {
    __nv_bfloat16 ha = __float2bfloat16(a);
    __nv_bfloat16 hb = __float2bfloat16(b);
    uint16_t ua = *reinterpret_cast<uint16_t*>(&ha);
    uint16_t ub = *reinterpret_cast<uint16_t*>(&hb);
    return (uint32_t)ua | ((uint32_t)ub << 16);
}
__device__ __forceinline__ float bf16_residual(float v) {
    __nv_bfloat16 h = __float2bfloat16(v);
    return v - __bfloat162float(h);
}
__device__ __forceinline__ void mma_bf16(float& c0, float& c1, float& c2, float& c3,
                                         uint32_t a0, uint32_t a1, uint32_t a2, uint32_t a3,
                                         uint32_t b0, uint32_t b1) {
    asm volatile(
        "mma.sync.aligned.m16n8k16.row.col.f32.bf16.bf16.f32 "
        "{%0,%1,%2,%3}, {%4,%5,%6,%7}, {%8,%9}, {%0,%1,%2,%3};"
        : "+f"(c0), "+f"(c1), "+f"(c2), "+f"(c3)
        : "r"(a0), "r"(a1), "r"(a2), "r"(a3), "r"(b0), "r"(b1));
}

// ================= prep =================
__global__ void k_prep1(const float* __restrict__ W_conv) {   // W_conv split + zero count
    for (int i = blockIdx.x * blockDim.x + threadIdx.x; i < IN_C * HID;
         i += gridDim.x * blockDim.x) {
        int k = i / HID, n = i % HID;
        float v = W_conv[i];
        g_wchi[n * IN_C + k] = __float2bfloat16(v);
        g_wclo[n * IN_C + k] = __float2bfloat16(bf16_residual(v));
    }
    for (int i = blockIdx.x * blockDim.x + threadIdx.x; i < N_NODES;
         i += gridDim.x * blockDim.x)
        g_count[i] = 0;
}

__global__ void k_prep2(const float* __restrict__ W_lin,      // W_lin split + bias2
                        const float* __restrict__ b_conv,
                        const float* __restrict__ b_lin) {
    int gt = blockIdx.x * blockDim.x + threadIdx.x;
    for (int i = gt; i < HID * IN_C; i += gridDim.x * blockDim.x) {
        int k = i / IN_C, n = i % IN_C;
        float v = W_lin[i];
        g_wlhi[n * HID + k] = __float2bfloat16(v);
        g_wllo[n * HID + k] = __float2bfloat16(bf16_residual(v));
    }
    if (gt < IN_C) {
        float s = b_lin[gt];
        #pragma unroll 4
        for (int k = 0; k < HID; k++) s += b_conv[k] * W_lin[k * IN_C + gt];
        g_bias2[gt] = s;
    }
}

// ================= GEMM1: 1024 threads (32 warps), pipelined =================
#define W_STRIDE 264                         // bf16 per W smem row (528B)
#define SW_HI    0
#define SW_LO    (HID * W_STRIDE * 2)        // 67584
#define SA_BASE  (2 * HID * W_STRIDE * 2)    // 135168
#define A_STRIDE 48
#define A_HALF   (128 * A_STRIDE)            // 6144
#define SA_BUF   (2 * A_HALF)                // 12288
#define G1_SMEM  (SA_BASE + 2 * SA_BUF)      // 159744

__global__ __launch_bounds__(1024, 1)
void gemm1_mma(const float* __restrict__ x) {
    extern __shared__ char smem[];
    const int tid  = threadIdx.x;
    const int wid  = tid >> 5;        // 0..31
    const int lane = tid & 31;
    const int g    = lane >> 2;
    const int tg   = lane & 3;
    const int wm   = wid >> 2;        // 0..7 -> 16-row strip
    const int wn   = wid & 3;         // 0..3 -> 32-col strip
    const int rowBase = blockIdx.x * 128;

    // stage W^T hi/lo (once)
    for (int idx = tid; idx < 128 * 32; idx += 1024) {
        int n = idx >> 5;
        int q = idx & 31;
        *reinterpret_cast<uint4*>(smem + SW_HI + n * (W_STRIDE * 2) + q * 16) =
            *reinterpret_cast<const uint4*>(&g_wchi[n * IN_C + q * 8]);
        *reinterpret_cast<uint4*>(smem + SW_LO + n * (W_STRIDE * 2) + q * 16) =
            *reinterpret_cast<const uint4*>(&g_wclo[n * IN_C + q * 8]);
    }

    // A staging identity: 8 threads per row, each loads float2 (2 k) per chunk
    const int r  = tid >> 3;                  // 0..127
    const int q2 = tid & 7;                   // 0..7
    const int grow = rowBase + r;
    const bool valid = (grow < N_NODES);
    const float* xrow = x + (size_t)grow * IN_C + q2 * 2;
    const int sa_off = r * A_STRIDE + q2 * 4;

    // prologue: chunk 0 -> buf 0
    {
        float2 f = make_float2(0.f, 0.f);
        if (valid) f = *reinterpret_cast<const float2*>(xrow);
        *reinterpret_cast<uint32_t*>(smem + SA_BASE + sa_off) = pack_bf16(f.x, f.y);
        *reinterpret_cast<uint32_t*>(smem + SA_BASE + A_HALF + sa_off) =
            pack_bf16(bf16_residual(f.x), bf16_residual(f.y));
    }

    float c[4][4];
    #pragma unroll
    for (int nt = 0; nt < 4; nt++)
        #pragma unroll
        for (int q = 0; q < 4; q++) c[nt][q] = 0.0f;

    __syncthreads();

    for (int kc = 0; kc < 16; kc++) {
        const int p = kc & 1;
        const char* bufA = smem + SA_BASE + p * SA_BUF;

        // prefetch next chunk
        float2 nf = make_float2(0.f, 0.f);
        if (kc < 15 && valid)
            nf = *reinterpret_cast<const float2*>(xrow + (kc + 1) * 16);

        // A fragments (one 16-row m-tile, hi+lo)
        uint32_t ah[4], al[4];
        {
            int row = wm * 16 + g;
            const char* base = bufA + row * A_STRIDE + tg * 4;
            ah[0] = *reinterpret_cast<const uint32_t*>(base);
            ah[1] = *reinterpret_cast<const uint32_t*>(base + 8 * A_STRIDE);
            ah[2] = *reinterpret_cast<const uint32_t*>(base + 16);
            ah[3] = *reinterpret_cast<const uint32_t*>(base + 8 * A_STRIDE + 16);
            al[0] = *reinterpret_cast<const uint32_t*>(base + A_HALF);
            al[1] = *reinterpret_cast<const uint32_t*>(base + A_HALF + 8 * A_STRIDE);
            al[2] = *reinterpret_cast<const uint32_t*>(base + A_HALF + 16);
            al[3] = *reinterpret_cast<const uint32_t*>(base + A_HALF + 8 * A_STRIDE + 16);
        }

        #pragma unroll
        for (int nt = 0; nt < 4; nt++) {
            int n = wn * 32 + nt * 8 + g;
            int wbase = n * (W_STRIDE * 2) + kc * 32 + tg * 4;
            uint32_t bh0 = *reinterpret_cast<uint32_t*>(smem + SW_HI + wbase);
            uint32_t bh1 = *reinterpret_cast<uint32_t*>(smem + SW_HI + wbase + 16);
            uint32_t bl0 = *reinterpret_cast<uint32_t*>(smem + SW_LO + wbase);
            uint32_t bl1 = *reinterpret_cast<uint32_t*>(smem + SW_LO + wbase + 16);
            mma_bf16(c[nt][0], c[nt][1], c[nt][2], c[nt][3],
                     ah[0], ah[1], ah[2], ah[3], bh0, bh1);
            mma_bf16(c[nt][0], c[nt][1], c[nt][2], c[nt][3],
                     ah[0], ah[1], ah[2], ah[3], bl0, bl1);
            mma_bf16(c[nt][0], c[nt][1], c[nt][2], c[nt][3],
                     al[0], al[1], al[2], al[3], bh0, bh1);
        }

        if (kc < 15) {
            char* nbuf = smem + SA_BASE + (1 - p) * SA_BUF;
            *reinterpret_cast<uint32_t*>(nbuf + sa_off) = pack_bf16(nf.x, nf.y);
            *reinterpret_cast<uint32_t*>(nbuf + A_HALF + sa_off) =
                pack_bf16(bf16_residual(nf.x), bf16_residual(nf.y));
            __syncthreads();
        }
    }

    // epilogue
    {
        int r0 = rowBase + wm * 16 + g;
        int r1 = r0 + 8;
        #pragma unroll
        for (int nt = 0; nt < 4; nt++) {
            int col = wn * 32 + nt * 8 + tg * 2;
            if (r0 < N_NODES)
                *reinterpret_cast<float2*>(&g_hs[(size_t)r0 * HID + col]) =
                    make_float2(c[nt][0], c[nt][1]);
            if (r1 < N_NODES)
                *reinterpret_cast<float2*>(&g_hs[(size_t)r1 * HID + col]) =
                    make_float2(c[nt][2], c[nt][3]);
        }
    }
}

// ================= CSR build =================
__global__ void k_count(const int* __restrict__ dst) {
    for (int e = blockIdx.x * blockDim.x + threadIdx.x; e < N_EDGES;
         e += gridDim.x * blockDim.x)
        atomicAdd(&g_count[dst[e]], 1);
}

__global__ void k_scan1() {
    __shared__ int sh[SCAN_B];
    int i = blockIdx.x * SCAN_B + threadIdx.x;
    int v = (i < N_NODES) ? g_count[i] : 0;
    sh[threadIdx.x] = v;
    __syncthreads();
    #pragma unroll
    for (int o = 1; o < SCAN_B; o <<= 1) {
        int t = (threadIdx.x >= o) ? sh[threadIdx.x - o] : 0;
        __syncthreads();
        sh[threadIdx.x] += t;
        __syncthreads();
    }
    if (i < N_NODES) g_rowptr[i] = sh[threadIdx.x] - v;
    if (threadIdx.x == SCAN_B - 1) g_blocksum[blockIdx.x] = sh[SCAN_B - 1];
}

// merged scan2+scan3: each block reduces blocksum[0..bid) itself
__global__ void k_scan3m() {
    __shared__ int sh[256];
    const int bid = blockIdx.x;
    const int t = threadIdx.x;
    sh[t] = (t < SCAN_NB && t < bid) ? g_blocksum[t] : 0;
    __syncthreads();
    #pragma unroll
    for (int s = 128; s > 0; s >>= 1) {
        if (t < s) sh[t] += sh[t + s];
        __syncthreads();
    }
    const int off = sh[0];
    int i = bid * SCAN_B + t;
    if (i < N_NODES) {
        int r = g_rowptr[i] + off;
        g_rowptr[i] = r;
        g_cursor[i] = r;
        g_dinv[i]   = rsqrtf((float)(g_count[i] + 1));
    }
    if (bid == 0 && t == 0) g_rowptr[N_NODES] = N_EDGES;
}

__global__ void k_fill(const int* __restrict__ src, const int* __restrict__ dst) {
    for (int e = blockIdx.x * blockDim.x + threadIdx.x; e < N_EDGES;
         e += gridDim.x * blockDim.x) {
        int p = atomicAdd(&g_cursor[dst[e]], 1);
        g_col[p] = src[e];
    }
}

// ================= FUSED gather + HMMA GEMM2 (64-node tiles, 2 CTA/SM) =================
#define F2_PAD   272
#define F2_WPAD  144
#define F2_SA_HI 0
#define F2_SA_LO (64 * F2_PAD)                  // 17408
#define F2_SW_HI (2 * 64 * F2_PAD)              // 34816
#define F2_SW_LO (F2_SW_HI + 256 * F2_WPAD)     // 71680
#define F2_SMEM  (F2_SW_LO + 256 * F2_WPAD)     // 108544

__global__ __launch_bounds__(512, 2)
void k_fused2(float* __restrict__ out) {
    extern __shared__ char smem[];
    const int tid = threadIdx.x;
    const int w   = tid >> 5;        // 0..15
    const int l   = tid & 31;
    const int rowBase = blockIdx.x * 64;

    // ---- gather 64 nodes (4 per warp) ----
    const float4* hs4 = reinterpret_cast<const float4*>(g_hs);
    #pragma unroll
    for (int q = 0; q < 4; q++) {
        int nLocal = q * 16 + w;
        int i = rowBase + nLocal;
        float4 acc = make_float4(0.f, 0.f, 0.f, 0.f);
        if (i < N_NODES) {
            float di = g_dinv[i];
            float4 v = hs4[(size_t)i * 32 + l];
            acc.x = v.x * di; acc.y = v.y * di; acc.z = v.z * di; acc.w = v.w * di;
            int e  = g_rowptr[i];
            int e1 = g_rowptr[i + 1];
            for (; e + 2 <= e1; e += 2) {
                int j0 = g_col[e];
                int j1 = g_col[e + 1];
                float d0 = g_dinv[j0];
                float d1 = g_dinv[j1];
                float4 u0 = hs4[(size_t)j0 * 32 + l];
                float4 u1 = hs4[(size_t)j1 * 32 + l];
                acc.x += u0.x * d0 + u1.x * d1;
                acc.y += u0.y * d0 + u1.y * d1;
                acc.z += u0.z * d0 + u1.z * d1;
                acc.w += u0.w * d0 + u1.w * d1;
            }
            if (e < e1) {
                int j = g_col[e];
                float dj = g_dinv[j];
                float4 u = hs4[(size_t)j * 32 + l];
                acc.x += u.x * dj; acc.y += u.y * dj;
                acc.z += u.z * dj; acc.w += u.w * dj;
            }
            acc.x *= di; acc.y *= di; acc.z *= di; acc.w *= di;
        }
        uint2 hi, lo;
        hi.x = pack_bf16(acc.x, acc.y);
        hi.y = pack_bf16(acc.z, acc.w);
        lo.x = pack_bf16(bf16_residual(acc.x), bf16_residual(acc.y));
        lo.y = pack_bf16(bf16_residual(acc.z), bf16_residual(acc.w));
        *reinterpret_cast<uint2*>(smem + F2_SA_HI + nLocal * F2_PAD + l * 8) = hi;
        *reinterpret_cast<uint2*>(smem + F2_SA_LO + nLocal * F2_PAD + l * 8) = lo;
    }
    __syncthreads();

    // ---- HMMA: out[64,256] = agg @ W_lin, K split into two 64-wide passes ----
    const int g  = l >> 2;
    const int tg = l & 3;
    const int wm = w >> 3;            // 0..1
    const int wn = w & 7;             // 0..7

    float c[2][4][4];
    #pragma unroll
    for (int mt = 0; mt < 2; mt++)
        #pragma unroll
        for (int nt = 0; nt < 4; nt++)
            #pragma unroll
            for (int q = 0; q < 4; q++) c[mt][nt][q] = 0.0f;

    #pragma unroll
    for (int pass = 0; pass < 2; pass++) {
        for (int idx = tid; idx < 256 * 8; idx += 512) {
            int n  = idx >> 3;
            int q8 = idx & 7;
            *reinterpret_cast<uint4*>(smem + F2_SW_HI + n * F2_WPAD + q8 * 16) =
                *reinterpret_cast<const uint4*>(&g_wlhi[n * HID + pass * 64 + q8 * 8]);
            *reinterpret_cast<uint4*>(smem + F2_SW_LO + n * F2_WPAD + q8 * 16) =
                *reinterpret_cast<const uint4*>(&g_wllo[n * HID + pass * 64 + q8 * 8]);
        }
        __syncthreads();

        #pragma unroll
        for (int kc = 0; kc < 4; kc++) {
            #pragma unroll
            for (int mt = 0; mt < 2; mt++) {
                int row = wm * 32 + mt * 16 + g;
                int abase = row * F2_PAD + pass * 128 + kc * 32 + tg * 4;
                uint32_t ah0 = *reinterpret_cast<uint32_t*>(smem + F2_SA_HI + abase);
                uint32_t ah1 = *reinterpret_cast<uint32_t*>(smem + F2_SA_HI + abase + 8 * F2_PAD);
                uint32_t ah2 = *reinterpret_cast<uint32_t*>(smem + F2_SA_HI + abase + 16);
                uint32_t ah3 = *reinterpret_cast<uint32_t*>(smem + F2_SA_HI + abase + 8 * F2_PAD + 16);
                uint32_t al0 = *reinterpret_cast<uint32_t*>(smem + F2_SA_LO + abase);
                uint32_t al1 = *reinterpret_cast<uint32_t*>(smem + F2_SA_LO + abase + 8 * F2_PAD);
                uint32_t al2 = *reinterpret_cast<uint32_t*>(smem + F2_SA_LO + abase + 16);
                uint32_t al3 = *reinterpret_cast<uint32_t*>(smem + F2_SA_LO + abase + 8 * F2_PAD + 16);
                #pragma unroll
                for (int nt = 0; nt < 4; nt++) {
                    int n = wn * 32 + nt * 8 + g;
                    int wbase = n * F2_WPAD + kc * 32 + tg * 4;
                    uint32_t bh0 = *reinterpret_cast<uint32_t*>(smem + F2_SW_HI + wbase);
                    uint32_t bh1 = *reinterpret_cast<uint32_t*>(smem + F2_SW_HI + wbase + 16);
                    uint32_t bl0 = *reinterpret_cast<uint32_t*>(smem + F2_SW_LO + wbase);
                    uint32_t bl1 = *reinterpret_cast<uint32_t*>(smem + F2_SW_LO + wbase + 16);
                    mma_bf16(c[mt][nt][0], c[mt][nt][1], c[mt][nt][2], c[mt][nt][3],
                             ah0, ah1, ah2, ah3, bh0, bh1);
                    mma_bf16(c[mt][nt][0], c[mt][nt][1], c[mt][nt][2], c[mt][nt][3],
                             ah0, ah1, ah2, ah3, bl0, bl1);
                    mma_bf16(c[mt][nt][0], c[mt][nt][1], c[mt][nt][2], c[mt][nt][3],
                             al0, al1, al2, al3, bh0, bh1);
                }
            }
        }
        if (pass == 0) __syncthreads();
    }

    // ---- epilogue ----
    #pragma unroll
    for (int mt = 0; mt < 2; mt++) {
        int r0 = rowBase + wm * 32 + mt * 16 + g;
        int r1 = r0 + 8;
        #pragma unroll
        for (int nt = 0; nt < 4; nt++) {
            int col = wn * 32 + nt * 8 + tg * 2;
            float b0 = g_bias2[col], b1 = g_bias2[col + 1];
            if (r0 < N_NODES)
                *reinterpret_cast<float2*>(&out[(size_t)r0 * IN_C + col]) =
                    make_float2(c[mt][nt][0] + b0, c[mt][nt][1] + b1);
            if (r1 < N_NODES)
                *reinterpret_cast<float2*>(&out[(size_t)r1 * IN_C + col]) =
                    make_float2(c[mt][nt][2] + b0, c[mt][nt][3] + b1);
        }
    }
}

// ================= launch =================
extern "C" void kernel_launch(void* const* d_in, const int* in_sizes, int n_in,
                              void* d_out, int out_size) {
    const float* x      = nullptr;
    const int*   eidx   = nullptr;
    const float* W_conv = nullptr;
    const float* W_lin  = nullptr;
    const float* b_conv = nullptr;
    const float* b_lin  = nullptr;

    for (int i = 0; i < n_in; i++) {
        int sz = in_sizes[i];
        const void* p = d_in[i];
        if      (sz == N_NODES * IN_C) x = (const float*)p;
        else if (sz == 2 * N_EDGES)    eidx = (const int*)p;
        else if (sz == IN_C * HID) { if (!W_conv) W_conv = (const float*)p;
                                     else         W_lin  = (const float*)p; }
        else if (sz == HID)            b_conv = (const float*)p;
        else if (sz == IN_C)           b_lin  = (const float*)p;
    }
    if (!x || !eidx || !W_conv || !W_lin || !b_conv || !b_lin) {
        x      = (const float*)d_in[0];
        eidx   = (const int*)d_in[1];
        W_conv = (const float*)d_in[2];
        b_conv = (const float*)d_in[3];
        W_lin  = (const float*)d_in[4];
        b_lin  = (const float*)d_in[5];
    }

    float* out = (float*)d_out;
    const int* src = eidx;
    const int* dst = eidx + N_EDGES;

    static bool attr_set = false;
    if (!attr_set) {
        cudaFuncSetAttribute(gemm1_mma, cudaFuncAttributeMaxDynamicSharedMemorySize, G1_SMEM);
        cudaFuncSetAttribute(k_fused2, cudaFuncAttributeMaxDynamicSharedMemorySize, F2_SMEM);
        attr_set = true;
    }

    k_prep1<<<196, 256>>>(W_conv);
    k_prep2<<<64, 256>>>(W_lin, b_conv, b_lin);
    k_count<<<3125, 256>>>(dst);
    gemm1_mma<<<(N_NODES + 127) / 128, 1024, G1_SMEM>>>(x);   // 4th: profiled

    k_scan1<<<SCAN_NB, SCAN_B>>>();
    k_scan3m<<<SCAN_NB, SCAN_B>>>();
    k_fill<<<3125, 256>>>(src, dst);

    k_fused2<<<(N_NODES + 63) / 64, 512, F2_SMEM>>>(out);
}

// round 13
// speedup vs baseline: 1.8558x; 1.0366x over previous
#include <cuda_runtime.h>
#include <cuda_bf16.h>
#include <cstdint>

#define N_NODES 50000
#define IN_C    256
#define HID     128
#define N_EDGES 800000
#define SCAN_B  256
#define SCAN_NB ((N_NODES + SCAN_B - 1) / SCAN_B)   // 196

// ---- device scratch: referenced ONLY from device code ----
__device__ float g_hs[N_NODES * HID];      // h = x @ W_conv (raw)
__device__ int   g_count[N_NODES];
__device__ int   g_rowptr[N_NODES + 1];
__device__ int   g_cursor[N_NODES];
__device__ int   g_col[N_EDGES];
__device__ float g_dinv[N_NODES];
__device__ float g_bias2[IN_C];
__device__ int   g_blocksum[SCAN_NB];
__device__ __nv_bfloat16 g_wchi[HID * IN_C];   // W_conv^T [n][k]
__device__ __nv_bfloat16 g_wclo[HID * IN_C];
__device__ __nv_bfloat16 g_wlhi[IN_C * HID];   // W_lin^T  [n][k]
__device__ __nv_bfloat16 g_wllo[IN_C * HID];

// ================= helpers =================
__device__ __forceinline__ uint32_t pack_bf16(float a, float b) {
    __nv_bfloat16 ha = __float2bfloat16(a);
    __nv_bfloat16 hb = __float2bfloat16(b);
    uint16_t ua = *reinterpret_cast<uint16_t*>(&ha);
    uint16_t ub = *reinterpret_cast<uint16_t*>(&hb);
    return (uint32_t)ua | ((uint32_t)ub << 16);
}
__device__ __forceinline__ float bf16_residual(float v) {
    __nv_bfloat16 h = __float2bfloat16(v);
    return v - __bfloat162float(h);
}
__device__ __forceinline__ void mma_bf16(float& c0, float& c1, float& c2, float& c3,
                                         uint32_t a0, uint32_t a1, uint32_t a2, uint32_t a3,
                                         uint32_t b0, uint32_t b1) {
    asm volatile(
        "mma.sync.aligned.m16n8k16.row.col.f32.bf16.bf16.f32 "
        "{%0,%1,%2,%3}, {%4,%5,%6,%7}, {%8,%9}, {%0,%1,%2,%3};"
        : "+f"(c0), "+f"(c1), "+f"(c2), "+f"(c3)
        : "r"(a0), "r"(a1), "r"(a2), "r"(a3), "r"(b0), "r"(b1));
}
__device__ __forceinline__ uint32_t smem_addr_u32(const void* p) {
    uint32_t a;
    asm("{ .reg .u64 t; cvta.to.shared.u64 t, %1; cvt.u32.u64 %0, t; }" : "=r"(a) : "l"(p));
    return a;
}
__device__ __forceinline__ void ldmx4(uint32_t& r0, uint32_t& r1, uint32_t& r2, uint32_t& r3,
                                      uint32_t addr) {
    asm volatile("ldmatrix.sync.aligned.m8n8.x4.shared.b16 {%0,%1,%2,%3}, [%4];"
                 : "=r"(r0), "=r"(r1), "=r"(r2), "=r"(r3) : "r"(addr));
}

// ================= prep =================
__global__ void k_prep1(const float* __restrict__ W_conv) {   // W_conv split + zero count
    for (int i = blockIdx.x * blockDim.x + threadIdx.x; i < IN_C * HID;
         i += gridDim.x * blockDim.x) {
        int k = i / HID, n = i % HID;
        float v = W_conv[i];
        g_wchi[n * IN_C + k] = __float2bfloat16(v);
        g_wclo[n * IN_C + k] = __float2bfloat16(bf16_residual(v));
    }
    for (int i = blockIdx.x * blockDim.x + threadIdx.x; i < N_NODES;
         i += gridDim.x * blockDim.x)
        g_count[i] = 0;
}

__global__ void k_prep2(const float* __restrict__ W_lin,      // W_lin split + bias2
                        const float* __restrict__ b_conv,
                        const float* __restrict__ b_lin) {
    int gt = blockIdx.x * blockDim.x + threadIdx.x;
    for (int i = gt; i < HID * IN_C; i += gridDim.x * blockDim.x) {
        int k = i / IN_C, n = i % IN_C;
        float v = W_lin[i];
        g_wlhi[n * HID + k] = __float2bfloat16(v);
        g_wllo[n * HID + k] = __float2bfloat16(bf16_residual(v));
    }
    if (gt < IN_C) {
        float s = b_lin[gt];
        #pragma unroll 4
        for (int k = 0; k < HID; k++) s += b_conv[k] * W_lin[k * IN_C + gt];
        g_bias2[gt] = s;
    }
}

// ================= GEMM1: 1024 threads, pipelined, ldmatrix frags =================
#define W_STRIDE 264                         // bf16 per W smem row (528B)
#define SW_HI    0
#define SW_LO    (HID * W_STRIDE * 2)        // 67584
#define SA_BASE  (2 * HID * W_STRIDE * 2)    // 135168
#define A_STRIDE 48
#define A_HALF   (128 * A_STRIDE)            // 6144
#define SA_BUF   (2 * A_HALF)                // 12288
#define G1_SMEM  (SA_BASE + 2 * SA_BUF)      // 159744

__global__ __launch_bounds__(1024, 1)
void gemm1_mma(const float* __restrict__ x) {
    extern __shared__ char smem[];
    const uint32_t sb = smem_addr_u32(smem);
    const int tid  = threadIdx.x;
    const int wid  = tid >> 5;        // 0..31
    const int lane = tid & 31;
    const int g    = lane >> 2;
    const int tg   = lane & 3;
    const int wm   = wid >> 2;        // 0..7 -> 16-row strip
    const int wn   = wid & 3;         // 0..3 -> 32-col strip
    const int rowBase = blockIdx.x * 128;

    // stage W^T hi/lo (once)
    for (int idx = tid; idx < 128 * 32; idx += 1024) {
        int n = idx >> 5;
        int q = idx & 31;
        *reinterpret_cast<uint4*>(smem + SW_HI + n * (W_STRIDE * 2) + q * 16) =
            *reinterpret_cast<const uint4*>(&g_wchi[n * IN_C + q * 8]);
        *reinterpret_cast<uint4*>(smem + SW_LO + n * (W_STRIDE * 2) + q * 16) =
            *reinterpret_cast<const uint4*>(&g_wclo[n * IN_C + q * 8]);
    }

    // A staging identity: 8 threads per row, each loads float2 (2 k) per chunk
    const int r  = tid >> 3;                  // 0..127
    const int q2 = tid & 7;                   // 0..7
    const int grow = rowBase + r;
    const bool valid = (grow < N_NODES);
    const float* xrow = x + (size_t)grow * IN_C + q2 * 2;
    const int sa_off = r * A_STRIDE + q2 * 4;

    // ---- ldmatrix per-thread addresses ----
    const int lj = lane >> 3;                 // matrix index 0..3
    const int lr = lane & 7;                  // row within matrix
    // A (m16k16 x4): row = wm*16 + (lj&1)*8 + lr, col16 = (lj>>1)*16 bytes
    const uint32_t aAddr0 = sb + SA_BASE +
        (uint32_t)((wm * 16 + (lj & 1) * 8 + lr) * A_STRIDE + (lj >> 1) * 16);
    // B (two n8k16 tiles per x4): pair p covers nt=2p,2p+1
    //   n = wn*32 + p*16 + (lj>>1)*8 + lr ; k16 = (lj&1)*16 bytes
    uint32_t bAddr[2];
    #pragma unroll
    for (int p = 0; p < 2; p++)
        bAddr[p] = sb + SW_HI +
            (uint32_t)((wn * 32 + p * 16 + (lj >> 1) * 8 + lr) * (W_STRIDE * 2) +
                       (lj & 1) * 16);

    // prologue: chunk 0 -> buf 0
    {
        float2 f = make_float2(0.f, 0.f);
        if (valid) f = *reinterpret_cast<const float2*>(xrow);
        *reinterpret_cast<uint32_t*>(smem + SA_BASE + sa_off) = pack_bf16(f.x, f.y);
        *reinterpret_cast<uint32_t*>(smem + SA_BASE + A_HALF + sa_off) =
            pack_bf16(bf16_residual(f.x), bf16_residual(f.y));
    }

    float c[4][4];
    #pragma unroll
    for (int nt = 0; nt < 4; nt++)
        #pragma unroll
        for (int q = 0; q < 4; q++) c[nt][q] = 0.0f;

    __syncthreads();

    for (int kc = 0; kc < 16; kc++) {
        const int p = kc & 1;
        const uint32_t aBuf = aAddr0 + (uint32_t)(p * SA_BUF);

        // prefetch next chunk
        float2 nf = make_float2(0.f, 0.f);
        if (kc < 15 && valid)
            nf = *reinterpret_cast<const float2*>(xrow + (kc + 1) * 16);

        // A fragments hi/lo via ldmatrix.x4
        uint32_t ah[4], al[4];
        ldmx4(ah[0], ah[1], ah[2], ah[3], aBuf);
        ldmx4(al[0], al[1], al[2], al[3], aBuf + A_HALF);

        // B pairs: load 4 frags (2 nt) at a time, hi+lo, then 6 MMAs each
        #pragma unroll
        for (int pr = 0; pr < 2; pr++) {
            uint32_t bh[4], bl[4];
            uint32_t ba = bAddr[pr] + (uint32_t)(kc * 32);
            ldmx4(bh[0], bh[1], bh[2], bh[3], ba);
            ldmx4(bl[0], bl[1], bl[2], bl[3], ba + (uint32_t)(SW_LO - SW_HI));
            #pragma unroll
            for (int s = 0; s < 2; s++) {
                int nt = pr * 2 + s;
                mma_bf16(c[nt][0], c[nt][1], c[nt][2], c[nt][3],
                         ah[0], ah[1], ah[2], ah[3], bh[s * 2], bh[s * 2 + 1]);
                mma_bf16(c[nt][0], c[nt][1], c[nt][2], c[nt][3],
                         ah[0], ah[1], ah[2], ah[3], bl[s * 2], bl[s * 2 + 1]);
                mma_bf16(c[nt][0], c[nt][1], c[nt][2], c[nt][3],
                         al[0], al[1], al[2], al[3], bh[s * 2], bh[s * 2 + 1]);
            }
        }

        if (kc < 15) {
            char* nbuf = smem + SA_BASE + (1 - p) * SA_BUF;
            *reinterpret_cast<uint32_t*>(nbuf + sa_off) = pack_bf16(nf.x, nf.y);
            *reinterpret_cast<uint32_t*>(nbuf + A_HALF + sa_off) =
                pack_bf16(bf16_residual(nf.x), bf16_residual(nf.y));
            __syncthreads();
        }
    }

    // epilogue
    {
        int r0 = rowBase + wm * 16 + g;
        int r1 = r0 + 8;
        #pragma unroll
        for (int nt = 0; nt < 4; nt++) {
            int col = wn * 32 + nt * 8 + tg * 2;
            if (r0 < N_NODES)
                *reinterpret_cast<float2*>(&g_hs[(size_t)r0 * HID + col]) =
                    make_float2(c[nt][0], c[nt][1]);
            if (r1 < N_NODES)
                *reinterpret_cast<float2*>(&g_hs[(size_t)r1 * HID + col]) =
                    make_float2(c[nt][2], c[nt][3]);
        }
    }
}

// ================= CSR build =================
__global__ void k_count(const int* __restrict__ dst) {
    for (int e = blockIdx.x * blockDim.x + threadIdx.x; e < N_EDGES;
         e += gridDim.x * blockDim.x)
        atomicAdd(&g_count[dst[e]], 1);
}

__global__ void k_scan1() {
    __shared__ int sh[SCAN_B];
    int i = blockIdx.x * SCAN_B + threadIdx.x;
    int v = (i < N_NODES) ? g_count[i] : 0;
    sh[threadIdx.x] = v;
    __syncthreads();
    #pragma unroll
    for (int o = 1; o < SCAN_B; o <<= 1) {
        int t = (threadIdx.x >= o) ? sh[threadIdx.x - o] : 0;
        __syncthreads();
        sh[threadIdx.x] += t;
        __syncthreads();
    }
    if (i < N_NODES) g_rowptr[i] = sh[threadIdx.x] - v;
    if (threadIdx.x == SCAN_B - 1) g_blocksum[blockIdx.x] = sh[SCAN_B - 1];
}

__global__ void k_scan3m() {
    __shared__ int sh[256];
    const int bid = blockIdx.x;
    const int t = threadIdx.x;
    sh[t] = (t < SCAN_NB && t < bid) ? g_blocksum[t] : 0;
    __syncthreads();
    #pragma unroll
    for (int s = 128; s > 0; s >>= 1) {
        if (t < s) sh[t] += sh[t + s];
        __syncthreads();
    }
    const int off = sh[0];
    int i = bid * SCAN_B + t;
    if (i < N_NODES) {
        int r = g_rowptr[i] + off;
        g_rowptr[i] = r;
        g_cursor[i] = r;
        g_dinv[i]   = rsqrtf((float)(g_count[i] + 1));
    }
    if (bid == 0 && t == 0) g_rowptr[N_NODES] = N_EDGES;
}

__global__ void k_fill(const int* __restrict__ src, const int* __restrict__ dst) {
    for (int e = blockIdx.x * blockDim.x + threadIdx.x; e < N_EDGES;
         e += gridDim.x * blockDim.x) {
        int p = atomicAdd(&g_cursor[dst[e]], 1);
        g_col[p] = src[e];
    }
}

// ================= FUSED gather + HMMA GEMM2 (unchanged from R12) =================
#define F2_PAD   272
#define F2_WPAD  144
#define F2_SA_HI 0
#define F2_SA_LO (64 * F2_PAD)                  // 17408
#define F2_SW_HI (2 * 64 * F2_PAD)              // 34816
#define F2_SW_LO (F2_SW_HI + 256 * F2_WPAD)     // 71680
#define F2_SMEM  (F2_SW_LO + 256 * F2_WPAD)     // 108544

__global__ __launch_bounds__(512, 2)
void k_fused2(float* __restrict__ out) {
    extern __shared__ char smem[];
    const int tid = threadIdx.x;
    const int w   = tid >> 5;
    const int l   = tid & 31;
    const int rowBase = blockIdx.x * 64;

    const float4* hs4 = reinterpret_cast<const float4*>(g_hs);
    #pragma unroll
    for (int q = 0; q < 4; q++) {
        int nLocal = q * 16 + w;
        int i = rowBase + nLocal;
        float4 acc = make_float4(0.f, 0.f, 0.f, 0.f);
        if (i < N_NODES) {
            float di = g_dinv[i];
            float4 v = hs4[(size_t)i * 32 + l];
            acc.x = v.x * di; acc.y = v.y * di; acc.z = v.z * di; acc.w = v.w * di;
            int e  = g_rowptr[i];
            int e1 = g_rowptr[i + 1];
            for (; e + 2 <= e1; e += 2) {
                int j0 = g_col[e];
                int j1 = g_col[e + 1];
                float d0 = g_dinv[j0];
                float d1 = g_dinv[j1];
                float4 u0 = hs4[(size_t)j0 * 32 + l];
                float4 u1 = hs4[(size_t)j1 * 32 + l];
                acc.x += u0.x * d0 + u1.x * d1;
                acc.y += u0.y * d0 + u1.y * d1;
                acc.z += u0.z * d0 + u1.z * d1;
                acc.w += u0.w * d0 + u1.w * d1;
            }
            if (e < e1) {
                int j = g_col[e];
                float dj = g_dinv[j];
                float4 u = hs4[(size_t)j * 32 + l];
                acc.x += u.x * dj; acc.y += u.y * dj;
                acc.z += u.z * dj; acc.w += u.w * dj;
            }
            acc.x *= di; acc.y *= di; acc.z *= di; acc.w *= di;
        }
        uint2 hi, lo;
        hi.x = pack_bf16(acc.x, acc.y);
        hi.y = pack_bf16(acc.z, acc.w);
        lo.x = pack_bf16(bf16_residual(acc.x), bf16_residual(acc.y));
        lo.y = pack_bf16(bf16_residual(acc.z), bf16_residual(acc.w));
        *reinterpret_cast<uint2*>(smem + F2_SA_HI + nLocal * F2_PAD + l * 8) = hi;
        *reinterpret_cast<uint2*>(smem + F2_SA_LO + nLocal * F2_PAD + l * 8) = lo;
    }
    __syncthreads();

    const int g  = l >> 2;
    const int tg = l & 3;
    const int wm = w >> 3;
    const int wn = w & 7;

    float c[2][4][4];
    #pragma unroll
    for (int mt = 0; mt < 2; mt++)
        #pragma unroll
        for (int nt = 0; nt < 4; nt++)
            #pragma unroll
            for (int q = 0; q < 4; q++) c[mt][nt][q] = 0.0f;

    #pragma unroll
    for (int pass = 0; pass < 2; pass++) {
        for (int idx = tid; idx < 256 * 8; idx += 512) {
            int n  = idx >> 3;
            int q8 = idx & 7;
            *reinterpret_cast<uint4*>(smem + F2_SW_HI + n * F2_WPAD + q8 * 16) =
                *reinterpret_cast<const uint4*>(&g_wlhi[n * HID + pass * 64 + q8 * 8]);
            *reinterpret_cast<uint4*>(smem + F2_SW_LO + n * F2_WPAD + q8 * 16) =
                *reinterpret_cast<const uint4*>(&g_wllo[n * HID + pass * 64 + q8 * 8]);
        }
        __syncthreads();

        #pragma unroll
        for (int kc = 0; kc < 4; kc++) {
            #pragma unroll
            for (int mt = 0; mt < 2; mt++) {
                int row = wm * 32 + mt * 16 + g;
                int abase = row * F2_PAD + pass * 128 + kc * 32 + tg * 4;
                uint32_t ah0 = *reinterpret_cast<uint32_t*>(smem + F2_SA_HI + abase);
                uint32_t ah1 = *reinterpret_cast<uint32_t*>(smem + F2_SA_HI + abase + 8 * F2_PAD);
                uint32_t ah2 = *reinterpret_cast<uint32_t*>(smem + F2_SA_HI + abase + 16);
                uint32_t ah3 = *reinterpret_cast<uint32_t*>(smem + F2_SA_HI + abase + 8 * F2_PAD + 16);
                uint32_t al0 = *reinterpret_cast<uint32_t*>(smem + F2_SA_LO + abase);
                uint32_t al1 = *reinterpret_cast<uint32_t*>(smem + F2_SA_LO + abase + 8 * F2_PAD);
                uint32_t al2 = *reinterpret_cast<uint32_t*>(smem + F2_SA_LO + abase + 16);
                uint32_t al3 = *reinterpret_cast<uint32_t*>(smem + F2_SA_LO + abase + 8 * F2_PAD + 16);
                #pragma unroll
                for (int nt = 0; nt < 4; nt++) {
                    int n = wn * 32 + nt * 8 + g;
                    int wbase = n * F2_WPAD + kc * 32 + tg * 4;
                    uint32_t bh0 = *reinterpret_cast<uint32_t*>(smem + F2_SW_HI + wbase);
                    uint32_t bh1 = *reinterpret_cast<uint32_t*>(smem + F2_SW_HI + wbase + 16);
                    uint32_t bl0 = *reinterpret_cast<uint32_t*>(smem + F2_SW_LO + wbase);
                    uint32_t bl1 = *reinterpret_cast<uint32_t*>(smem + F2_SW_LO + wbase + 16);
                    mma_bf16(c[mt][nt][0], c[mt][nt][1], c[mt][nt][2], c[mt][nt][3],
                             ah0, ah1, ah2, ah3, bh0, bh1);
                    mma_bf16(c[mt][nt][0], c[mt][nt][1], c[mt][nt][2], c[mt][nt][3],
                             ah0, ah1, ah2, ah3, bl0, bl1);
                    mma_bf16(c[mt][nt][0], c[mt][nt][1], c[mt][nt][2], c[mt][nt][3],
                             al0, al1, al2, al3, bh0, bh1);
                }
            }
        }
        if (pass == 0) __syncthreads();
    }

    #pragma unroll
    for (int mt = 0; mt < 2; mt++) {
        int r0 = rowBase + wm * 32 + mt * 16 + g;
        int r1 = r0 + 8;
        #pragma unroll
        for (int nt = 0; nt < 4; nt++) {
            int col = wn * 32 + nt * 8 + tg * 2;
            float b0 = g_bias2[col], b1 = g_bias2[col + 1];
            if (r0 < N_NODES)
                *reinterpret_cast<float2*>(&out[(size_t)r0 * IN_C + col]) =
                    make_float2(c[mt][nt][0] + b0, c[mt][nt][1] + b1);
            if (r1 < N_NODES)
                *reinterpret_cast<float2*>(&out[(size_t)r1 * IN_C + col]) =
                    make_float2(c[mt][nt][2] + b0, c[mt][nt][3] + b1);
        }
    }
}

// ================= launch =================
extern "C" void kernel_launch(void* const* d_in, const int* in_sizes, int n_in,
                              void* d_out, int out_size) {
    const float* x      = nullptr;
    const int*   eidx   = nullptr;
    const float* W_conv = nullptr;
    const float* W_lin  = nullptr;
    const float* b_conv = nullptr;
    const float* b_lin  = nullptr;

    for (int i = 0; i < n_in; i++) {
        int sz = in_sizes[i];
        const void* p = d_in[i];
        if      (sz == N_NODES * IN_C) x = (const float*)p;
        else if (sz == 2 * N_EDGES)    eidx = (const int*)p;
        else if (sz == IN_C * HID) { if (!W_conv) W_conv = (const float*)p;
                                     else         W_lin  = (const float*)p; }
        else if (sz == HID)            b_conv = (const float*)p;
        else if (sz == IN_C)           b_lin  = (const float*)p;
    }
    if (!x || !eidx || !W_conv || !W_lin || !b_conv || !b_lin) {
        x      = (const float*)d_in[0];
        eidx   = (const int*)d_in[1];
        W_conv = (const float*)d_in[2];
        b_conv = (const float*)d_in[3];
        W_lin  = (const float*)d_in[4];
        b_lin  = (const float*)d_in[5];
    }

    float* out = (float*)d_out;
    const int* src = eidx;
    const int* dst = eidx + N_EDGES;

    static bool attr_set = false;
    if (!attr_set) {
        cudaFuncSetAttribute(gemm1_mma, cudaFuncAttributeMaxDynamicSharedMemorySize, G1_SMEM);
        cudaFuncSetAttribute(k_fused2, cudaFuncAttributeMaxDynamicSharedMemorySize, F2_SMEM);
        attr_set = true;
    }

    k_prep1<<<196, 256>>>(W_conv);
    k_prep2<<<64, 256>>>(W_lin, b_conv, b_lin);
    k_count<<<3125, 256>>>(dst);
    gemm1_mma<<<(N_NODES + 127) / 128, 1024, G1_SMEM>>>(x);   // 4th: profiled

    k_scan1<<<SCAN_NB, SCAN_B>>>();
    k_scan3m<<<SCAN_NB, SCAN_B>>>();
    k_fill<<<3125, 256>>>(src, dst);

    k_fused2<<<(N_NODES + 63) / 64, 512, F2_SMEM>>>(out);
}